// round 10
// baseline (speedup 1.0000x reference)
#include <cuda_runtime.h>
#include <cuda_bf16.h>
#include <math_constants.h>
#include <cstdint>

#define B_  4
#define L_  4096
#define D_  256
#define BL_ (B_ * L_)
#define NSPLIT 4
#define KEYS_PER_SPLIT (L_ / NSPLIT)            /* 1024 */
#define TILES_PER_SPLIT (KEYS_PER_SPLIT / 128)  /* 8 */
#define CHUNKS_PER_SPLIT (TILES_PER_SPLIT * 8)  /* 64 */

// bf16 scratch, pair-interleaved d-layout: within each 16-d group, pair
// order [0,4,1,5,2,6,3,7], so m16n8k16 fragment words are 8B-contiguous.
__device__ __align__(1024) __nv_bfloat16 g_Q[BL_ * D_];
__device__ __align__(1024) __nv_bfloat16 g_KB[BL_ * D_];
__device__ __align__(1024) __nv_bfloat16 g_Xb[BL_ * D_];
__device__ __align__(1024) __nv_bfloat16 g_Wqb[D_ * D_];
__device__ __align__(1024) __nv_bfloat16 g_Wkb[D_ * D_];
__device__ __align__(1024) float4 g_part[NSPLIT][BL_];   // (l, ax, ay)
__device__ int g_cnt[B_ * 32];                           // merge counters

// ---------------------------------------------------------------------------
// helpers
// ---------------------------------------------------------------------------
__device__ __forceinline__ uint32_t smem_u32(const void* p) {
    uint32_t a;
    asm("{ .reg .u64 t; cvta.to.shared.u64 t, %1; cvt.u32.u64 %0, t; }"
        : "=r"(a) : "l"(p));
    return a;
}

__device__ __forceinline__ float ex2f(float x) {
    float y;
    asm("ex2.approx.f32 %0, %1;" : "=f"(y) : "f"(x));
    return y;
}

__device__ __forceinline__ void cp16(uint32_t dst, const void* src) {
    asm volatile("cp.async.cg.shared.global [%0], [%1], 16;"
                 :: "r"(dst), "l"(src) : "memory");
}
__device__ __forceinline__ void cp_commit() {
    asm volatile("cp.async.commit_group;" ::: "memory");
}
__device__ __forceinline__ void cp_wait2() {
    asm volatile("cp.async.wait_group 2;" ::: "memory");
}

__device__ __forceinline__ void lds64(uint32_t& v0, uint32_t& v1, uint32_t a) {
    asm volatile("ld.shared.v2.b32 {%0, %1}, [%2];"
                 : "=r"(v0), "=r"(v1) : "r"(a));
}

#define MMA_BF16(d, a0, a1, a2, a3, b0, b1) \
    asm volatile("mma.sync.aligned.m16n8k16.row.col.f32.bf16.bf16.f32 " \
                 "{%0,%1,%2,%3},{%4,%5,%6,%7},{%8,%9},{%0,%1,%2,%3};" \
                 : "+f"((d)[0]), "+f"((d)[1]), "+f"((d)[2]), "+f"((d)[3]) \
                 : "r"(a0), "r"(a1), "r"(a2), "r"(a3), "r"(b0), "r"(b1))

// phys pair-slot for logical pair j within a row (128 pairs)
__device__ __forceinline__ int pslot(int j) {
    int jj = j & 7;
    int s = (jj < 4) ? 2 * jj : 2 * (jj - 4) + 1;
    return (j >> 3) * 8 + s;
}

// ---------------------------------------------------------------------------
// Kernel 0: round latents / Wq / Wk to bf16 (pair-interleaved); zero counters.
// ---------------------------------------------------------------------------
#define XPAIRS (BL_ * 128)
#define WPAIRS (D_ * 128)
#define CVT_TOTAL (XPAIRS + 2 * WPAIRS)

__global__ void __launch_bounds__(256)
convert_kernel(const float* __restrict__ latents,
               const float* __restrict__ Wq, const float* __restrict__ Wk) {
    int idx = blockIdx.x * 256 + threadIdx.x;
    if (idx < B_ * 32) g_cnt[idx] = 0;
    const float* src;
    __nv_bfloat162* dst;
    if (idx < XPAIRS) {
        src = latents; dst = (__nv_bfloat162*)g_Xb;
    } else if (idx < XPAIRS + WPAIRS) {
        idx -= XPAIRS; src = Wq; dst = (__nv_bfloat162*)g_Wqb;
    } else {
        idx -= XPAIRS + WPAIRS; src = Wk; dst = (__nv_bfloat162*)g_Wkb;
    }
    int row = idx >> 7, ps = idx & 127;
    int g16 = ps >> 3, s = ps & 7;
    int j = (s & 1) ? (s >> 1) + 4 : (s >> 1);
    int d = g16 * 16 + 2 * j;
    float lo = __ldg(&src[(size_t)row * D_ + d]);
    float hi = __ldg(&src[(size_t)row * D_ + d + 1]);
    dst[(size_t)row * 128 + ps] = __floats2bfloat162_rn(lo, hi);
}

// ---------------------------------------------------------------------------
// Kernel 1: proj via mma.sync bf16. One CTA = 128 rows x BOTH Wq and Wk
// (X tile loaded once; 16-chunk W stream = 8 Wq + 8 Wk). Row L2-norm fused.
// 512 threads = 16 warps (warpm 0..3 x warpn 0..3), warp tile 32m x 64n.
// ---------------------------------------------------------------------------
#define PXST 528                             /* X row bytes (512 + 16) */
#define PWST 80                              /* W row bytes (64 + 16) */
#define P_SLOT (D_ * PWST)                   /* 20480 */
#define P_SMX 0
#define P_SMW (128 * PXST)                   /* 67584 */
#define P_RED (P_SMW + 4 * P_SLOT)           /* 149504 */
#define P_TOT (P_RED + 2048)                 /* 151552 */

__global__ void __launch_bounds__(512, 1)
proj_mma_kernel() {
    extern __shared__ __align__(1024) char smem[];
    const uint32_t sb = smem_u32(smem);
    const int tid  = threadIdx.x;
    const int lane = tid & 31;
    const int warp = tid >> 5;
    const int warpm = warp & 3, warpn = warp >> 2;   // 4 x 4
    const int g  = lane >> 2, t4 = lane & 3;
    const int row0 = blockIdx.x * 128;

    const __nv_bfloat16* __restrict__ Xg = g_Xb + (size_t)row0 * D_;

    // W-chunk cp.async offsets: 1024 cp16 per chunk, 2 per thread.
    const int wn0 = tid >> 2,           wo0 = (tid & 3) * 16;
    const int wn1 = (tid + 512) >> 2,   wo1 = ((tid + 512) & 3) * 16;
    const uint32_t wd0 = wn0 * PWST + wo0, wd1 = wn1 * PWST + wo1;
    const int ws0 = wn0 * D_ + wo0 / 2, ws1 = wn1 * D_ + wo1 / 2;

    // ---- prologue: X tile + first 3 W chunks ----
#pragma unroll
    for (int i = 0; i < 8; i++) {
        int seg = tid + 512 * i;            // 0..4095, 32 x 16B per row
        int row = seg >> 5, o = seg & 31;
        cp16(sb + P_SMX + row * PXST + o * 16, Xg + row * D_ + o * 8);
    }
    cp_commit();
#pragma unroll
    for (int gc = 0; gc < 3; gc++) {
        uint32_t slot = sb + P_SMW + (gc & 3) * P_SLOT;
        const __nv_bfloat16* src = g_Wqb + gc * 32;
        cp16(slot + wd0, src + ws0);
        cp16(slot + wd1, src + ws1);
        cp_commit();
    }

    float* __restrict__ red = (float*)(smem + P_RED);

    for (int which = 0; which < 2; which++) {
        float S[2][8][4];
#pragma unroll
        for (int mt = 0; mt < 2; mt++)
#pragma unroll
            for (int nb = 0; nb < 8; nb++)
#pragma unroll
                for (int r = 0; r < 4; r++) S[mt][nb][r] = 0.f;

        for (int c8 = 0; c8 < 8; c8++) {
            const int gc = which * 8 + c8;
            cp_wait2();
            __syncthreads();
            if (gc + 3 < 16) {
                int nc = gc + 3;
                uint32_t slot = sb + P_SMW + (nc & 3) * P_SLOT;
                const __nv_bfloat16* src =
                    (nc < 8 ? g_Wqb : g_Wkb) + (nc & 7) * 32;
                cp16(slot + wd0, src + ws0);
                cp16(slot + wd1, src + ws1);
            }
            cp_commit();

            const uint32_t slot = sb + P_SMW + (gc & 3) * P_SLOT;
#pragma unroll
            for (int ks = 0; ks < 2; ks++) {
                const int cb = (c8 * 32 + ks * 16) * 2 + t4 * 8;
                uint32_t a02[2][2], a13[2][2];
#pragma unroll
                for (int mt = 0; mt < 2; mt++) {
                    uint32_t qb = sb + P_SMX +
                        (warpm * 32 + mt * 16 + g) * PXST + cb;
                    lds64(a02[mt][0], a02[mt][1], qb);
                    lds64(a13[mt][0], a13[mt][1], qb + 8 * PXST);
                }
                uint32_t kb = slot + (warpn * 64 + g) * PWST + ks * 32 + t4 * 8;
#pragma unroll
                for (int nb = 0; nb < 8; nb++) {
                    uint32_t b0, b1;
                    lds64(b0, b1, kb + nb * 8 * PWST);
                    MMA_BF16(S[0][nb], a02[0][0], a13[0][0], a02[0][1],
                             a13[0][1], b0, b1);
                    MMA_BF16(S[1][nb], a02[1][0], a13[1][0], a02[1][1],
                             a13[1][1], b0, b1);
                }
            }
        }

        // ---- row sum-of-squares: quad shfl + cross-warpn exchange ----
        __syncthreads();   // last chunk's LDS done before red reuse below
#pragma unroll
        for (int mt = 0; mt < 2; mt++)
#pragma unroll
            for (int h = 0; h < 2; h++) {
                float v = 0.f;
#pragma unroll
                for (int nb = 0; nb < 8; nb++) {
                    v = fmaf(S[mt][nb][2 * h], S[mt][nb][2 * h], v);
                    v = fmaf(S[mt][nb][2 * h + 1], S[mt][nb][2 * h + 1], v);
                }
                v += __shfl_xor_sync(0xffffffffu, v, 1);
                v += __shfl_xor_sync(0xffffffffu, v, 2);
                if (t4 == 0)
                    red[warpn * 128 + warpm * 32 + mt * 16 + h * 8 + g] = v;
            }
        __syncthreads();

        __nv_bfloat162* __restrict__ Out =
            (__nv_bfloat162*)(which ? g_KB : g_Q);
#pragma unroll
        for (int mt = 0; mt < 2; mt++)
#pragma unroll
            for (int h = 0; h < 2; h++) {
                int rowl = warpm * 32 + mt * 16 + h * 8 + g;
                float tot = (red[rowl] + red[128 + rowl]) +
                            (red[256 + rowl] + red[384 + rowl]);
                float scale = 1.0f / fmaxf(sqrtf(tot), 1e-12f);
                __nv_bfloat162* orow = Out + (size_t)(row0 + rowl) * 128;
#pragma unroll
                for (int nb = 0; nb < 8; nb++) {
                    int j = warpn * 32 + nb * 4 + t4;
                    orow[pslot(j)] = __floats2bfloat162_rn(
                        S[mt][nb][2 * h] * scale, S[mt][nb][2 * h + 1] * scale);
                }
            }
        __syncthreads();   // red reads done before next pass writes
    }
}

// ---------------------------------------------------------------------------
// Kernel 2: flash attention partials + fused finalize (last CTA merges).
// Grid (32 qtiles, B, NSPLIT); 2 CTAs co-resident per SM.
// CTA: 128 q x KEYS_PER_SPLIT keys; 256 threads = 8 warps (4m x 2n).
// ---------------------------------------------------------------------------
#define QST   528
#define KST   80
#define SLOT_B (128 * KST)                   /* 10240 */
#define SM_Q   0
#define SM_K   (128 * QST)                   /* 67584 */
#define SM_C   (SM_K + 4 * SLOT_B)           /* 108544 */
#define SM_R   (SM_C + 1024)                 /* 109568 */
#define SM_TOT (SM_R + 4096)                 /* 113664 */

#define SCALE_EX2 14.4269504088896340f       /* 10 * log2(e) */

__global__ void __launch_bounds__(256, 2)
attn_kernel(const float* __restrict__ coords,
            const float* __restrict__ alpha_p,
            float* __restrict__ out_new,
            float* __restrict__ out_disp) {
    extern __shared__ __align__(1024) char smem[];
    __shared__ int s_last;
    const uint32_t sb = smem_u32(smem);
    const int tid  = threadIdx.x;
    const int lane = tid & 31;
    const int warp = tid >> 5;
    const int warpm = warp & 3, warpn = warp >> 2;
    const int g  = lane >> 2, t4 = lane & 3;
    const int b  = blockIdx.y;
    const int q0 = blockIdx.x * 128;
    const int split = blockIdx.z;

    const __nv_bfloat16* __restrict__ Qg = g_Q + (size_t)(b * L_ + q0) * D_;
    const float2* __restrict__ Cg2 = (const float2*)coords + (size_t)b * L_ +
                                     split * KEYS_PER_SPLIT;

    const int kr0 = tid >> 2,          ko0 = (tid & 3) * 16;
    const int kr1 = (tid + 256) >> 2,  ko1 = ((tid + 256) & 3) * 16;
    const uint32_t kdst0 = kr0 * KST + ko0;
    const uint32_t kdst1 = kr1 * KST + ko1;
    const __nv_bfloat16* __restrict__ KgT =
        g_KB + (size_t)(b * L_ + split * KEYS_PER_SPLIT) * D_;
    const int ksrc0 = kr0 * D_ + ko0 / 2;
    const int ksrc1 = kr1 * D_ + ko1 / 2;

#pragma unroll
    for (int i = 0; i < 16; i++) {
        int seg = tid + 256 * i;
        int row = seg >> 5, o = seg & 31;
        cp16(sb + SM_Q + row * QST + o * 16, Qg + row * D_ + o * 8);
    }
    cp_commit();
#pragma unroll
    for (int gc = 0; gc < 3; gc++) {
        uint32_t slot = sb + SM_K + (gc & 3) * SLOT_B;
        const __nv_bfloat16* src = KgT + (gc & 7) * 32;
        cp16(slot + kdst0, src + ksrc0);
        cp16(slot + kdst1, src + ksrc1);
        cp_commit();
    }

    float l[4], ax[4], ay[4];
#pragma unroll
    for (int s = 0; s < 4; s++) { l[s] = 0.f; ax[s] = 0.f; ay[s] = 0.f; }

    for (int t = 0; t < TILES_PER_SPLIT; t++) {
        __syncthreads();
        if (tid < 128)
            ((float2*)(smem + SM_C))[tid] = Cg2[t * 128 + tid];

        float S[2][8][4];
#pragma unroll
        for (int mt = 0; mt < 2; mt++)
#pragma unroll
            for (int nb = 0; nb < 8; nb++)
#pragma unroll
                for (int r = 0; r < 4; r++) S[mt][nb][r] = 0.f;

        for (int c8 = 0; c8 < 8; c8++) {
            const int gc = t * 8 + c8;
            cp_wait2();
            __syncthreads();
            if (gc + 3 < CHUNKS_PER_SPLIT) {
                int nc = gc + 3;
                uint32_t slot = sb + SM_K + (nc & 3) * SLOT_B;
                const __nv_bfloat16* src =
                    KgT + (nc >> 3) * (128 * D_) + (nc & 7) * 32;
                cp16(slot + kdst0, src + ksrc0);
                cp16(slot + kdst1, src + ksrc1);
            }
            cp_commit();

            const uint32_t slot = sb + SM_K + (gc & 3) * SLOT_B;
#pragma unroll
            for (int ks = 0; ks < 2; ks++) {
                const int cb = (c8 * 32 + ks * 16) * 2 + t4 * 8;
                uint32_t a02[2][2], a13[2][2];
#pragma unroll
                for (int mt = 0; mt < 2; mt++) {
                    uint32_t qb = sb + SM_Q +
                        (warpm * 32 + mt * 16 + g) * QST + cb;
                    lds64(a02[mt][0], a02[mt][1], qb);
                    lds64(a13[mt][0], a13[mt][1], qb + 8 * QST);
                }
                uint32_t kb = slot + (warpn * 64 + g) * KST + ks * 32 + t4 * 8;
#pragma unroll
                for (int nb = 0; nb < 8; nb++) {
                    uint32_t b0, b1;
                    lds64(b0, b1, kb + nb * 8 * KST);
                    MMA_BF16(S[0][nb], a02[0][0], a13[0][0], a02[0][1],
                             a13[0][1], b0, b1);
                    MMA_BF16(S[1][nb], a02[1][0], a13[1][0], a02[1][1],
                             a13[1][1], b0, b1);
                }
            }
        }

        const float4* __restrict__ C4 = (const float4*)(smem + SM_C);
#pragma unroll
        for (int mt = 0; mt < 2; mt++) {
            const int s0 = mt * 2, s1 = mt * 2 + 1;
#pragma unroll
            for (int nb = 0; nb < 8; nb++) {
                float4 cc = C4[warpn * 32 + nb * 4 + t4];
                float p0 = ex2f(S[mt][nb][0] * SCALE_EX2);
                float p1 = ex2f(S[mt][nb][1] * SCALE_EX2);
                float p2 = ex2f(S[mt][nb][2] * SCALE_EX2);
                float p3 = ex2f(S[mt][nb][3] * SCALE_EX2);
                l[s0] += p0 + p1;
                ax[s0] = fmaf(p0, cc.x, ax[s0]); ay[s0] = fmaf(p0, cc.y, ay[s0]);
                ax[s0] = fmaf(p1, cc.z, ax[s0]); ay[s0] = fmaf(p1, cc.w, ay[s0]);
                l[s1] += p2 + p3;
                ax[s1] = fmaf(p2, cc.x, ax[s1]); ay[s1] = fmaf(p2, cc.y, ay[s1]);
                ax[s1] = fmaf(p3, cc.z, ax[s1]); ay[s1] = fmaf(p3, cc.w, ay[s1]);
            }
        }
    }

    float4* __restrict__ red = (float4*)(smem + SM_R);
#pragma unroll
    for (int s = 0; s < 4; s++) {
#pragma unroll
        for (int off = 1; off < 4; off <<= 1) {
            l[s]  += __shfl_xor_sync(0xffffffffu, l[s],  off);
            ax[s] += __shfl_xor_sync(0xffffffffu, ax[s], off);
            ay[s] += __shfl_xor_sync(0xffffffffu, ay[s], off);
        }
        if (t4 == 0) {
            int rowl = warpm * 32 + (s >> 1) * 16 + (s & 1) * 8 + g;
            red[warpn * 128 + rowl] = make_float4(l[s], ax[s], ay[s], 0.f);
        }
    }
    __syncthreads();

    if (tid < 128) {
        float4 r0 = red[tid], r1 = red[128 + tid];
        g_part[split][b * L_ + q0 + tid] =
            make_float4(r0.x + r1.x, r0.y + r1.y, r0.z + r1.z, 0.f);
    }
    __threadfence();
    __syncthreads();
    if (tid == 0)
        s_last = atomicAdd(&g_cnt[b * 32 + blockIdx.x], 1);
    __syncthreads();

    // Last-arriving split CTA merges all partials and writes outputs.
    if (s_last == NSPLIT - 1 && tid < 128) {
        int i = b * L_ + q0 + tid;
        float lv = 0.f, axv = 0.f, ayv = 0.f;
#pragma unroll
        for (int sp = 0; sp < NSPLIT; sp++) {
            float4 p = g_part[sp][i];
            lv += p.x; axv += p.y; ayv += p.z;
        }
        float a = 1.0f / (1.0f + __expf(-alpha_p[0]));
        float inv = 1.0f / lv;
        float wx = axv * inv, wy = ayv * inv;
        float2 c = ((const float2*)coords)[i];
        float nx = a * wx + (1.0f - a) * c.x;
        float ny = a * wy + (1.0f - a) * c.y;
        out_new[2 * i + 0]  = nx;
        out_new[2 * i + 1]  = ny;
        out_disp[2 * i + 0] = nx - c.x;
        out_disp[2 * i + 1] = ny - c.y;
    }
}

// ---------------------------------------------------------------------------
// Inputs: latents, current_coords, Wq, Wk, alpha_raw, layer_idx.
// Output: concat(new_coords[B,L,2], displacement[B,L,2]) fp32.
// ---------------------------------------------------------------------------
extern "C" void kernel_launch(void* const* d_in, const int* in_sizes, int n_in,
                              void* d_out, int out_size) {
    const float* latents   = (const float*)d_in[0];
    const float* coords    = (const float*)d_in[1];
    const float* Wq        = (const float*)d_in[2];
    const float* Wk        = (const float*)d_in[3];
    const float* alpha_raw = (const float*)d_in[4];
    float* out = (float*)d_out;

    convert_kernel<<<(CVT_TOTAL + 255) / 256, 256>>>(latents, Wq, Wk);

    cudaFuncSetAttribute(proj_mma_kernel,
                         cudaFuncAttributeMaxDynamicSharedMemorySize, P_TOT);
    proj_mma_kernel<<<BL_ / 128, 512, P_TOT>>>();

    cudaFuncSetAttribute(attn_kernel,
                         cudaFuncAttributeMaxDynamicSharedMemorySize, SM_TOT);
    attn_kernel<<<dim3(L_ / 128, B_, NSPLIT), 256, SM_TOT>>>(
        coords, alpha_raw, out, out + BL_ * 2);
}

// round 11
// speedup vs baseline: 1.0534x; 1.0534x over previous
#include <cuda_runtime.h>
#include <cuda_bf16.h>
#include <math_constants.h>
#include <cstdint>

#define B_  4
#define L_  4096
#define D_  256
#define BL_ (B_ * L_)
#define NSPLIT 4
#define KEYS_PER_SPLIT (L_ / NSPLIT)            /* 1024 */
#define TILES_PER_SPLIT (KEYS_PER_SPLIT / 128)  /* 8 */
#define CHUNKS2 (TILES_PER_SPLIT * 4)           /* 32 x 64-d chunks */

// bf16 scratch, pair-interleaved d-layout: within each 16-d group, pair
// order [0,4,1,5,2,6,3,7], so m16n8k16 fragment words are 8B-contiguous.
__device__ __align__(1024) __nv_bfloat16 g_Q[BL_ * D_];
__device__ __align__(1024) __nv_bfloat16 g_KB[BL_ * D_];
__device__ __align__(1024) __nv_bfloat16 g_Xb[BL_ * D_];
__device__ __align__(1024) __nv_bfloat16 g_Wqb[D_ * D_];
__device__ __align__(1024) __nv_bfloat16 g_Wkb[D_ * D_];
__device__ __align__(1024) float4 g_part[NSPLIT][BL_];   // (l, ax, ay)
__device__ int g_cnt[B_ * 32];                           // merge counters

// ---------------------------------------------------------------------------
// helpers
// ---------------------------------------------------------------------------
__device__ __forceinline__ uint32_t smem_u32(const void* p) {
    uint32_t a;
    asm("{ .reg .u64 t; cvta.to.shared.u64 t, %1; cvt.u32.u64 %0, t; }"
        : "=r"(a) : "l"(p));
    return a;
}

__device__ __forceinline__ float ex2f(float x) {
    float y;
    asm("ex2.approx.f32 %0, %1;" : "=f"(y) : "f"(x));
    return y;
}

__device__ __forceinline__ void cp16(uint32_t dst, const void* src) {
    asm volatile("cp.async.cg.shared.global [%0], [%1], 16;"
                 :: "r"(dst), "l"(src) : "memory");
}
__device__ __forceinline__ void cp_commit() {
    asm volatile("cp.async.commit_group;" ::: "memory");
}
__device__ __forceinline__ void cp_wait0() {
    asm volatile("cp.async.wait_group 0;" ::: "memory");
}
__device__ __forceinline__ void cp_wait2() {
    asm volatile("cp.async.wait_group 2;" ::: "memory");
}

__device__ __forceinline__ void lds64(uint32_t& v0, uint32_t& v1, uint32_t a) {
    asm volatile("ld.shared.v2.b32 {%0, %1}, [%2];"
                 : "=r"(v0), "=r"(v1) : "r"(a));
}

#define MMA_BF16(d, a0, a1, a2, a3, b0, b1) \
    asm volatile("mma.sync.aligned.m16n8k16.row.col.f32.bf16.bf16.f32 " \
                 "{%0,%1,%2,%3},{%4,%5,%6,%7},{%8,%9},{%0,%1,%2,%3};" \
                 : "+f"((d)[0]), "+f"((d)[1]), "+f"((d)[2]), "+f"((d)[3]) \
                 : "r"(a0), "r"(a1), "r"(a2), "r"(a3), "r"(b0), "r"(b1))

// phys pair-slot for logical pair j within a row (128 pairs)
__device__ __forceinline__ int pslot(int j) {
    int jj = j & 7;
    int s = (jj < 4) ? 2 * jj : 2 * (jj - 4) + 1;
    return (j >> 3) * 8 + s;
}

// ---------------------------------------------------------------------------
// Kernel 0: round latents / Wq / Wk to bf16 (pair-interleaved); zero counters.
// Contiguous float2 reads; the interleave permutation is applied on the
// store side (4B scatter within 32B sectors -> still fully coalesced).
// ---------------------------------------------------------------------------
#define XPAIRS (BL_ * 128)
#define WPAIRS (D_ * 128)
#define CVT_TOTAL (XPAIRS + 2 * WPAIRS)

__global__ void __launch_bounds__(256)
convert_kernel(const float* __restrict__ latents,
               const float* __restrict__ Wq, const float* __restrict__ Wk) {
    int idx = blockIdx.x * 256 + threadIdx.x;
    if (idx < B_ * 32) g_cnt[idx] = 0;
    const float* src;
    __nv_bfloat162* dst;
    if (idx < XPAIRS) {
        src = latents; dst = (__nv_bfloat162*)g_Xb;
    } else if (idx < XPAIRS + WPAIRS) {
        idx -= XPAIRS; src = Wq; dst = (__nv_bfloat162*)g_Wqb;
    } else {
        idx -= XPAIRS + WPAIRS; src = Wk; dst = (__nv_bfloat162*)g_Wkb;
    }
    int row = idx >> 7, j = idx & 127;                 // logical pair j
    float2 v = __ldg((const float2*)src + (size_t)row * 128 + j);
    dst[(size_t)row * 128 + pslot(j)] = __floats2bfloat162_rn(v.x, v.y);
}

// ---------------------------------------------------------------------------
// Kernel 1: proj via mma.sync bf16. One CTA = 128 rows x BOTH Wq and Wk
// (X tile loaded once; 16-chunk W stream = 8 Wq + 8 Wk). Row L2-norm fused.
// 512 threads = 16 warps (warpm 0..3 x warpn 0..3), warp tile 32m x 64n.
// ---------------------------------------------------------------------------
#define PXST 528                             /* X row bytes (512 + 16) */
#define PWST 80                              /* W row bytes (64 + 16) */
#define P_SLOT (D_ * PWST)                   /* 20480 */
#define P_SMX 0
#define P_SMW (128 * PXST)                   /* 67584 */
#define P_RED (P_SMW + 4 * P_SLOT)           /* 149504 */
#define P_TOT (P_RED + 2048)                 /* 151552 */

__global__ void __launch_bounds__(512, 1)
proj_mma_kernel() {
    extern __shared__ __align__(1024) char smem[];
    const uint32_t sb = smem_u32(smem);
    const int tid  = threadIdx.x;
    const int lane = tid & 31;
    const int warp = tid >> 5;
    const int warpm = warp & 3, warpn = warp >> 2;   // 4 x 4
    const int g  = lane >> 2, t4 = lane & 3;
    const int row0 = blockIdx.x * 128;

    const __nv_bfloat16* __restrict__ Xg = g_Xb + (size_t)row0 * D_;

    // W-chunk cp.async offsets: 1024 cp16 per chunk, 2 per thread.
    const int wn0 = tid >> 2,           wo0 = (tid & 3) * 16;
    const int wn1 = (tid + 512) >> 2,   wo1 = ((tid + 512) & 3) * 16;
    const uint32_t wd0 = wn0 * PWST + wo0, wd1 = wn1 * PWST + wo1;
    const int ws0 = wn0 * D_ + wo0 / 2, ws1 = wn1 * D_ + wo1 / 2;

    // ---- prologue: X tile + first 3 W chunks ----
#pragma unroll
    for (int i = 0; i < 8; i++) {
        int seg = tid + 512 * i;            // 0..4095, 32 x 16B per row
        int row = seg >> 5, o = seg & 31;
        cp16(sb + P_SMX + row * PXST + o * 16, Xg + row * D_ + o * 8);
    }
    cp_commit();
#pragma unroll
    for (int gc = 0; gc < 3; gc++) {
        uint32_t slot = sb + P_SMW + (gc & 3) * P_SLOT;
        const __nv_bfloat16* src = g_Wqb + gc * 32;
        cp16(slot + wd0, src + ws0);
        cp16(slot + wd1, src + ws1);
        cp_commit();
    }

    float* __restrict__ red = (float*)(smem + P_RED);

    for (int which = 0; which < 2; which++) {
        float S[2][8][4];
#pragma unroll
        for (int mt = 0; mt < 2; mt++)
#pragma unroll
            for (int nb = 0; nb < 8; nb++)
#pragma unroll
                for (int r = 0; r < 4; r++) S[mt][nb][r] = 0.f;

        for (int c8 = 0; c8 < 8; c8++) {
            const int gc = which * 8 + c8;
            cp_wait2();
            __syncthreads();
            if (gc + 3 < 16) {
                int nc = gc + 3;
                uint32_t slot = sb + P_SMW + (nc & 3) * P_SLOT;
                const __nv_bfloat16* src =
                    (nc < 8 ? g_Wqb : g_Wkb) + (nc & 7) * 32;
                cp16(slot + wd0, src + ws0);
                cp16(slot + wd1, src + ws1);
            }
            cp_commit();

            const uint32_t slot = sb + P_SMW + (gc & 3) * P_SLOT;
#pragma unroll
            for (int ks = 0; ks < 2; ks++) {
                const int cb = (c8 * 32 + ks * 16) * 2 + t4 * 8;
                uint32_t a02[2][2], a13[2][2];
#pragma unroll
                for (int mt = 0; mt < 2; mt++) {
                    uint32_t qb = sb + P_SMX +
                        (warpm * 32 + mt * 16 + g) * PXST + cb;
                    lds64(a02[mt][0], a02[mt][1], qb);
                    lds64(a13[mt][0], a13[mt][1], qb + 8 * PXST);
                }
                uint32_t kb = slot + (warpn * 64 + g) * PWST + ks * 32 + t4 * 8;
#pragma unroll
                for (int nb = 0; nb < 8; nb++) {
                    uint32_t b0, b1;
                    lds64(b0, b1, kb + nb * 8 * PWST);
                    MMA_BF16(S[0][nb], a02[0][0], a13[0][0], a02[0][1],
                             a13[0][1], b0, b1);
                    MMA_BF16(S[1][nb], a02[1][0], a13[1][0], a02[1][1],
                             a13[1][1], b0, b1);
                }
            }
        }

        // ---- row sum-of-squares: quad shfl + cross-warpn exchange ----
        __syncthreads();   // last chunk's LDS done before red reuse below
#pragma unroll
        for (int mt = 0; mt < 2; mt++)
#pragma unroll
            for (int h = 0; h < 2; h++) {
                float v = 0.f;
#pragma unroll
                for (int nb = 0; nb < 8; nb++) {
                    v = fmaf(S[mt][nb][2 * h], S[mt][nb][2 * h], v);
                    v = fmaf(S[mt][nb][2 * h + 1], S[mt][nb][2 * h + 1], v);
                }
                v += __shfl_xor_sync(0xffffffffu, v, 1);
                v += __shfl_xor_sync(0xffffffffu, v, 2);
                if (t4 == 0)
                    red[warpn * 128 + warpm * 32 + mt * 16 + h * 8 + g] = v;
            }
        __syncthreads();

        __nv_bfloat162* __restrict__ Out =
            (__nv_bfloat162*)(which ? g_KB : g_Q);
#pragma unroll
        for (int mt = 0; mt < 2; mt++)
#pragma unroll
            for (int h = 0; h < 2; h++) {
                int rowl = warpm * 32 + mt * 16 + h * 8 + g;
                float tot = (red[rowl] + red[128 + rowl]) +
                            (red[256 + rowl] + red[384 + rowl]);
                float scale = 1.0f / fmaxf(sqrtf(tot), 1e-12f);
                __nv_bfloat162* orow = Out + (size_t)(row0 + rowl) * 128;
#pragma unroll
                for (int nb = 0; nb < 8; nb++) {
                    int j = warpn * 32 + nb * 4 + t4;
                    orow[pslot(j)] = __floats2bfloat162_rn(
                        S[mt][nb][2 * h] * scale, S[mt][nb][2 * h + 1] * scale);
                }
            }
        __syncthreads();   // red reads done before next pass writes
    }
}

// ---------------------------------------------------------------------------
// Kernel 2: flash attention partials + fused finalize (last CTA merges).
// Grid (32 qtiles, B, NSPLIT); 2 CTAs co-resident per SM.
// CTA: 128 q x KEYS_PER_SPLIT keys; 256 threads = 8 warps (4m x 2n).
// K streamed in 64-d x 128-key chunks, true double buffer (ring-2,
// wait_group 0, prefetch distance 1). Coords for the whole split preloaded.
// ---------------------------------------------------------------------------
#define QST   528
#define KST2  144                            /* 128B data + 16 pad */
#define SLOT2 (128 * KST2)                   /* 18432 */
#define SM_Q   0
#define SM_K   (128 * QST)                   /* 67584 */
#define SM_C   (SM_K + 2 * SLOT2)            /* 104448 */
#define SM_R   SM_K                          /* overlay on dead K slots */
#define SM_TOT (SM_C + KEYS_PER_SPLIT * 8)   /* 112640 */

#define SCALE_EX2 14.4269504088896340f       /* 10 * log2(e) */

__global__ void __launch_bounds__(256, 2)
attn_kernel(const float* __restrict__ coords,
            const float* __restrict__ alpha_p,
            float* __restrict__ out_new,
            float* __restrict__ out_disp) {
    extern __shared__ __align__(1024) char smem[];
    __shared__ int s_last;
    const uint32_t sb = smem_u32(smem);
    const int tid  = threadIdx.x;
    const int lane = tid & 31;
    const int warp = tid >> 5;
    const int warpm = warp & 3, warpn = warp >> 2;
    const int g  = lane >> 2, t4 = lane & 3;
    const int b  = blockIdx.y;
    const int q0 = blockIdx.x * 128;
    const int split = blockIdx.z;

    const __nv_bfloat16* __restrict__ Qg = g_Q + (size_t)(b * L_ + q0) * D_;
    const __nv_bfloat16* __restrict__ KgT =
        g_KB + (size_t)(b * L_ + split * KEYS_PER_SPLIT) * D_;
    const float2* __restrict__ Cg2 = (const float2*)coords + (size_t)b * L_ +
                                     split * KEYS_PER_SPLIT;

    // K-chunk cp.async offsets: 1024 cp16 per 64-d chunk, 4 per thread.
    uint32_t kdst[4];
    int ksrc[4];
#pragma unroll
    for (int i = 0; i < 4; i++) {
        int seg = tid + 256 * i;            // 0..1023; 8 x 16B per key row
        int kr = seg >> 3, ko = (seg & 7) * 16;
        kdst[i] = kr * KST2 + ko;
        ksrc[i] = kr * D_ + ko / 2;         // elements within chunk d-window
    }

    // ---- prologue: Q tile (async) + coords (STS) + chunk 0 (async) ----
#pragma unroll
    for (int i = 0; i < 16; i++) {
        int seg = tid + 256 * i;
        int row = seg >> 5, o = seg & 31;
        cp16(sb + SM_Q + row * QST + o * 16, Qg + row * D_ + o * 8);
    }
    cp_commit();
    ((float4*)(smem + SM_C))[tid]       = ((const float4*)Cg2)[tid];
    ((float4*)(smem + SM_C))[tid + 256] = ((const float4*)Cg2)[tid + 256];
#pragma unroll
    for (int i = 0; i < 4; i++)
        cp16(sb + SM_K + kdst[i], KgT + ksrc[i]);
    cp_commit();

    float l[4], ax[4], ay[4];
#pragma unroll
    for (int s = 0; s < 4; s++) { l[s] = 0.f; ax[s] = 0.f; ay[s] = 0.f; }

    const float4* __restrict__ C4 = (const float4*)(smem + SM_C);

    for (int t = 0; t < TILES_PER_SPLIT; t++) {
        float S[2][8][4];
#pragma unroll
        for (int mt = 0; mt < 2; mt++)
#pragma unroll
            for (int nb = 0; nb < 8; nb++)
#pragma unroll
                for (int r = 0; r < 4; r++) S[mt][nb][r] = 0.f;

        for (int c4 = 0; c4 < 4; c4++) {
            const int c = t * 4 + c4;
            cp_wait0();                     // chunk c landed
            __syncthreads();                // all warps done with chunk c-1
            if (c + 1 < CHUNKS2) {
                int nc = c + 1;
                uint32_t slot = sb + SM_K + (nc & 1) * SLOT2;
                const __nv_bfloat16* src =
                    KgT + (nc >> 2) * (128 * D_) + (nc & 3) * 64;
#pragma unroll
                for (int i = 0; i < 4; i++)
                    cp16(slot + kdst[i], src + ksrc[i]);
                cp_commit();
            }

            const uint32_t slot = sb + SM_K + (c & 1) * SLOT2;
#pragma unroll
            for (int ks = 0; ks < 4; ks++) {
                const int cb = (c4 * 4 + ks) * 32 + t4 * 8;
                uint32_t a02[2][2], a13[2][2];
#pragma unroll
                for (int mt = 0; mt < 2; mt++) {
                    uint32_t qb = sb + SM_Q +
                        (warpm * 32 + mt * 16 + g) * QST + cb;
                    lds64(a02[mt][0], a02[mt][1], qb);
                    lds64(a13[mt][0], a13[mt][1], qb + 8 * QST);
                }
                uint32_t kb = slot + (warpn * 64 + g) * KST2 + ks * 32 + t4 * 8;
#pragma unroll
                for (int nb = 0; nb < 8; nb++) {
                    uint32_t b0, b1;
                    lds64(b0, b1, kb + nb * 8 * KST2);
                    MMA_BF16(S[0][nb], a02[0][0], a13[0][0], a02[0][1],
                             a13[0][1], b0, b1);
                    MMA_BF16(S[1][nb], a02[1][0], a13[1][0], a02[1][1],
                             a13[1][1], b0, b1);
                }
            }
        }

        // ---- epilogue: p = 2^(s*10*log2e); accumulate l, ax, ay ----
#pragma unroll
        for (int mt = 0; mt < 2; mt++) {
            const int s0 = mt * 2, s1 = mt * 2 + 1;
#pragma unroll
            for (int nb = 0; nb < 8; nb++) {
                float4 cc = C4[t * 64 + warpn * 32 + nb * 4 + t4];
                float p0 = ex2f(S[mt][nb][0] * SCALE_EX2);
                float p1 = ex2f(S[mt][nb][1] * SCALE_EX2);
                float p2 = ex2f(S[mt][nb][2] * SCALE_EX2);
                float p3 = ex2f(S[mt][nb][3] * SCALE_EX2);
                l[s0] += p0 + p1;
                ax[s0] = fmaf(p0, cc.x, ax[s0]); ay[s0] = fmaf(p0, cc.y, ay[s0]);
                ax[s0] = fmaf(p1, cc.z, ax[s0]); ay[s0] = fmaf(p1, cc.w, ay[s0]);
                l[s1] += p2 + p3;
                ax[s1] = fmaf(p2, cc.x, ax[s1]); ay[s1] = fmaf(p2, cc.y, ay[s1]);
                ax[s1] = fmaf(p3, cc.z, ax[s1]); ay[s1] = fmaf(p3, cc.w, ay[s1]);
            }
        }
    }

    // ---- cross-lane + cross-warpn reduction (red overlays K slots) ----
    float4* __restrict__ red = (float4*)(smem + SM_R);
    __syncthreads();                        // K-slot LDS done before overlay
#pragma unroll
    for (int s = 0; s < 4; s++) {
#pragma unroll
        for (int off = 1; off < 4; off <<= 1) {
            l[s]  += __shfl_xor_sync(0xffffffffu, l[s],  off);
            ax[s] += __shfl_xor_sync(0xffffffffu, ax[s], off);
            ay[s] += __shfl_xor_sync(0xffffffffu, ay[s], off);
        }
        if (t4 == 0) {
            int rowl = warpm * 32 + (s >> 1) * 16 + (s & 1) * 8 + g;
            red[warpn * 128 + rowl] = make_float4(l[s], ax[s], ay[s], 0.f);
        }
    }
    __syncthreads();

    if (tid < 128) {
        float4 r0 = red[tid], r1 = red[128 + tid];
        g_part[split][b * L_ + q0 + tid] =
            make_float4(r0.x + r1.x, r0.y + r1.y, r0.z + r1.z, 0.f);
    }
    __threadfence();
    __syncthreads();
    if (tid == 0)
        s_last = atomicAdd(&g_cnt[b * 32 + blockIdx.x], 1);
    __syncthreads();

    // Last-arriving split CTA merges all partials and writes outputs.
    if (s_last == NSPLIT - 1 && tid < 128) {
        int i = b * L_ + q0 + tid;
        float lv = 0.f, axv = 0.f, ayv = 0.f;
#pragma unroll
        for (int sp = 0; sp < NSPLIT; sp++) {
            float4 p = g_part[sp][i];
            lv += p.x; axv += p.y; ayv += p.z;
        }
        float a = 1.0f / (1.0f + __expf(-alpha_p[0]));
        float inv = 1.0f / lv;
        float wx = axv * inv, wy = ayv * inv;
        float2 c = ((const float2*)coords)[i];
        float nx = a * wx + (1.0f - a) * c.x;
        float ny = a * wy + (1.0f - a) * c.y;
        out_new[2 * i + 0]  = nx;
        out_new[2 * i + 1]  = ny;
        out_disp[2 * i + 0] = nx - c.x;
        out_disp[2 * i + 1] = ny - c.y;
    }
}

// ---------------------------------------------------------------------------
// Inputs: latents, current_coords, Wq, Wk, alpha_raw, layer_idx.
// Output: concat(new_coords[B,L,2], displacement[B,L,2]) fp32.
// ---------------------------------------------------------------------------
extern "C" void kernel_launch(void* const* d_in, const int* in_sizes, int n_in,
                              void* d_out, int out_size) {
    const float* latents   = (const float*)d_in[0];
    const float* coords    = (const float*)d_in[1];
    const float* Wq        = (const float*)d_in[2];
    const float* Wk        = (const float*)d_in[3];
    const float* alpha_raw = (const float*)d_in[4];
    float* out = (float*)d_out;

    convert_kernel<<<(CVT_TOTAL + 255) / 256, 256>>>(latents, Wq, Wk);

    cudaFuncSetAttribute(proj_mma_kernel,
                         cudaFuncAttributeMaxDynamicSharedMemorySize, P_TOT);
    proj_mma_kernel<<<BL_ / 128, 512, P_TOT>>>();

    cudaFuncSetAttribute(attn_kernel,
                         cudaFuncAttributeMaxDynamicSharedMemorySize, SM_TOT);
    attn_kernel<<<dim3(L_ / 128, B_, NSPLIT), 256, SM_TOT>>>(
        coords, alpha_raw, out, out + BL_ * 2);
}

// round 13
// speedup vs baseline: 1.3776x; 1.3078x over previous
#include <cuda_runtime.h>
#include <cuda_bf16.h>
#include <math_constants.h>
#include <cstdint>

#define B_  4
#define L_  4096
#define D_  256
#define BL_ (B_ * L_)
#define NSPLIT 4
#define KEYS_PER_SPLIT (L_ / NSPLIT)            /* 1024 */
#define TILES_PER_SPLIT (KEYS_PER_SPLIT / 128)  /* 8 */
#define CHUNKS2 (TILES_PER_SPLIT * 4)           /* 32 x 64-d chunks */

// g_Q / g_KB: PLAIN row-major bf16 (row x 256 d contiguous) — ldmatrix layout.
// g_Wqb/g_Wkb: pair-interleaved (proj's internal lds64 path unchanged).
__device__ __align__(1024) __nv_bfloat16 g_Q[BL_ * D_];
__device__ __align__(1024) __nv_bfloat16 g_KB[BL_ * D_];
__device__ __align__(1024) __nv_bfloat16 g_Wqb[D_ * D_];
__device__ __align__(1024) __nv_bfloat16 g_Wkb[D_ * D_];
__device__ __align__(1024) float4 g_part[NSPLIT][BL_];   // (l, ax, ay)
__device__ int g_cnt[B_ * 32];                           // merge counters

// ---------------------------------------------------------------------------
// helpers
// ---------------------------------------------------------------------------
__device__ __forceinline__ uint32_t smem_u32(const void* p) {
    uint32_t a;
    asm("{ .reg .u64 t; cvta.to.shared.u64 t, %1; cvt.u32.u64 %0, t; }"
        : "=r"(a) : "l"(p));
    return a;
}

__device__ __forceinline__ float ex2f(float x) {
    float y;
    asm("ex2.approx.f32 %0, %1;" : "=f"(y) : "f"(x));
    return y;
}

__device__ __forceinline__ void cp16(uint32_t dst, const void* src) {
    asm volatile("cp.async.cg.shared.global [%0], [%1], 16;"
                 :: "r"(dst), "l"(src) : "memory");
}
__device__ __forceinline__ void cp_commit() {
    asm volatile("cp.async.commit_group;" ::: "memory");
}
__device__ __forceinline__ void cp_wait0() {
    asm volatile("cp.async.wait_group 0;" ::: "memory");
}
__device__ __forceinline__ void cp_wait2() {
    asm volatile("cp.async.wait_group 2;" ::: "memory");
}

__device__ __forceinline__ void lds64(uint32_t& v0, uint32_t& v1, uint32_t a) {
    asm volatile("ld.shared.v2.b32 {%0, %1}, [%2];"
                 : "=r"(v0), "=r"(v1) : "r"(a));
}

__device__ __forceinline__ void sts128(uint32_t a, uint32_t r0, uint32_t r1,
                                       uint32_t r2, uint32_t r3) {
    asm volatile("st.shared.v4.b32 [%0], {%1, %2, %3, %4};"
                 :: "r"(a), "r"(r0), "r"(r1), "r"(r2), "r"(r3) : "memory");
}

#define LDSM_X4(r0, r1, r2, r3, addr) \
    asm volatile("ldmatrix.sync.aligned.m8n8.x4.shared.b16 " \
                 "{%0, %1, %2, %3}, [%4];" \
                 : "=r"(r0), "=r"(r1), "=r"(r2), "=r"(r3) : "r"(addr))

#define MMA_BF16(d, a0, a1, a2, a3, b0, b1) \
    asm volatile("mma.sync.aligned.m16n8k16.row.col.f32.bf16.bf16.f32 " \
                 "{%0,%1,%2,%3},{%4,%5,%6,%7},{%8,%9},{%0,%1,%2,%3};" \
                 : "+f"((d)[0]), "+f"((d)[1]), "+f"((d)[2]), "+f"((d)[3]) \
                 : "r"(a0), "r"(a1), "r"(a2), "r"(a3), "r"(b0), "r"(b1))

// phys pair-slot for logical pair j within a row (128 pairs) — W only.
__device__ __forceinline__ int pslot(int j) {
    int jj = j & 7;
    int s = (jj < 4) ? 2 * jj : 2 * (jj - 4) + 1;
    return (j >> 3) * 8 + s;
}

__device__ __forceinline__ uint32_t bf2(float lo, float hi) {
    __nv_bfloat162 v = __floats2bfloat162_rn(lo, hi);
    return *(uint32_t*)&v;
}

// ---------------------------------------------------------------------------
// Kernel 0: round Wq / Wk to bf16 (pair-interleaved); zero merge counters.
// ---------------------------------------------------------------------------
#define WPAIRS (D_ * 128)

__global__ void __launch_bounds__(256)
convert_kernel(const float* __restrict__ Wq, const float* __restrict__ Wk) {
    int idx = blockIdx.x * 256 + threadIdx.x;     // 0 .. 2*WPAIRS-1
    if (idx < B_ * 32) g_cnt[idx] = 0;
    const float* src = (idx < WPAIRS) ? Wq : Wk;
    __nv_bfloat162* dst = (__nv_bfloat162*)((idx < WPAIRS) ? g_Wqb : g_Wkb);
    int i = (idx < WPAIRS) ? idx : idx - WPAIRS;
    int row = i >> 7, j = i & 127;
    float2 v = __ldg((const float2*)src + (size_t)row * 128 + j);
    dst[(size_t)row * 128 + pslot(j)] = __floats2bfloat162_rn(v.x, v.y);
}

// ---------------------------------------------------------------------------
// Kernel 1: proj via mma.sync bf16. One CTA = 128 rows x BOTH Wq and Wk.
// X read fp32 directly from latents (LDG -> bf16 pack -> interleaved STS).
// Row L2-norm fused; output written PLAIN row-major to g_Q / g_KB.
// 512 threads = 16 warps (warpm 0..3 x warpn 0..3), warp tile 32m x 64n.
// ---------------------------------------------------------------------------
#define PXST 528                             /* X row bytes (512 + 16) */
#define PWST 80                              /* W row bytes (64 + 16) */
#define P_SLOT (D_ * PWST)                   /* 20480 */
#define P_SMX 0
#define P_SMW (128 * PXST)                   /* 67584 */
#define P_RED (P_SMW + 4 * P_SLOT)           /* 149504 */
#define P_TOT (P_RED + 2048)                 /* 151552 */

__global__ void __launch_bounds__(512, 1)
proj_mma_kernel(const float* __restrict__ latents) {
    extern __shared__ __align__(1024) char smem[];
    const uint32_t sb = smem_u32(smem);
    const int tid  = threadIdx.x;
    const int lane = tid & 31;
    const int warp = tid >> 5;
    const int warpm = warp & 3, warpn = warp >> 2;   // 4 x 4
    const int g  = lane >> 2, t4 = lane & 3;
    const int row0 = blockIdx.x * 128;

    // W-chunk cp.async offsets: 1024 cp16 per chunk, 2 per thread.
    const int wn0 = tid >> 2,           wo0 = (tid & 3) * 16;
    const int wn1 = (tid + 512) >> 2,   wo1 = ((tid + 512) & 3) * 16;
    const uint32_t wd0 = wn0 * PWST + wo0, wd1 = wn1 * PWST + wo1;
    const int ws0 = wn0 * D_ + wo0 / 2, ws1 = wn1 * D_ + wo1 / 2;

    // ---- prologue: first 3 W chunks (async) + X fp32->bf16 interleaved ----
#pragma unroll
    for (int gc = 0; gc < 3; gc++) {
        uint32_t slot = sb + P_SMW + (gc & 3) * P_SLOT;
        const __nv_bfloat16* src = g_Wqb + gc * 32;
        cp16(slot + wd0, src + ws0);
        cp16(slot + wd1, src + ws1);
        cp_commit();
    }
    {
        const float4* __restrict__ Xf4 =
            (const float4*)(latents + (size_t)row0 * D_);
#pragma unroll
        for (int i = 0; i < 4; i++) {
            int idx = tid + 512 * i;            // 0..2047
            int r = idx >> 4, gg = idx & 15;    // row, 16-d group
            const float4* p = Xf4 + r * 64 + gg * 4;
            float4 v0 = __ldg(p + 0), v1 = __ldg(p + 1);
            float4 v2 = __ldg(p + 2), v3 = __ldg(p + 3);
            uint32_t p0 = bf2(v0.x, v0.y), p1 = bf2(v0.z, v0.w);
            uint32_t p2 = bf2(v1.x, v1.y), p3 = bf2(v1.z, v1.w);
            uint32_t p4 = bf2(v2.x, v2.y), p5 = bf2(v2.z, v2.w);
            uint32_t p6 = bf2(v3.x, v3.y), p7 = bf2(v3.z, v3.w);
            uint32_t sa = sb + P_SMX + r * PXST + gg * 32;
            sts128(sa,      p0, p4, p1, p5);    // slots 0-3
            sts128(sa + 16, p2, p6, p3, p7);    // slots 4-7
        }
    }

    float* __restrict__ red = (float*)(smem + P_RED);

    for (int which = 0; which < 2; which++) {
        float S[2][8][4];
#pragma unroll
        for (int mt = 0; mt < 2; mt++)
#pragma unroll
            for (int nb = 0; nb < 8; nb++)
#pragma unroll
                for (int r = 0; r < 4; r++) S[mt][nb][r] = 0.f;

        for (int c8 = 0; c8 < 8; c8++) {
            const int gc = which * 8 + c8;
            cp_wait2();
            __syncthreads();
            if (gc + 3 < 16) {
                int nc = gc + 3;
                uint32_t slot = sb + P_SMW + (nc & 3) * P_SLOT;
                const __nv_bfloat16* src =
                    (nc < 8 ? g_Wqb : g_Wkb) + (nc & 7) * 32;
                cp16(slot + wd0, src + ws0);
                cp16(slot + wd1, src + ws1);
            }
            cp_commit();

            const uint32_t slot = sb + P_SMW + (gc & 3) * P_SLOT;
#pragma unroll
            for (int ks = 0; ks < 2; ks++) {
                const int cb = (c8 * 32 + ks * 16) * 2 + t4 * 8;
                uint32_t a02[2][2], a13[2][2];
#pragma unroll
                for (int mt = 0; mt < 2; mt++) {
                    uint32_t qb = sb + P_SMX +
                        (warpm * 32 + mt * 16 + g) * PXST + cb;
                    lds64(a02[mt][0], a02[mt][1], qb);
                    lds64(a13[mt][0], a13[mt][1], qb + 8 * PXST);
                }
                uint32_t kb = slot + (warpn * 64 + g) * PWST + ks * 32 + t4 * 8;
#pragma unroll
                for (int nb = 0; nb < 8; nb++) {
                    uint32_t b0, b1;
                    lds64(b0, b1, kb + nb * 8 * PWST);
                    MMA_BF16(S[0][nb], a02[0][0], a13[0][0], a02[0][1],
                             a13[0][1], b0, b1);
                    MMA_BF16(S[1][nb], a02[1][0], a13[1][0], a02[1][1],
                             a13[1][1], b0, b1);
                }
            }
        }

        // ---- row sum-of-squares: quad shfl + cross-warpn exchange ----
        __syncthreads();   // last chunk's LDS done before red reuse below
#pragma unroll
        for (int mt = 0; mt < 2; mt++)
#pragma unroll
            for (int h = 0; h < 2; h++) {
                float v = 0.f;
#pragma unroll
                for (int nb = 0; nb < 8; nb++) {
                    v = fmaf(S[mt][nb][2 * h], S[mt][nb][2 * h], v);
                    v = fmaf(S[mt][nb][2 * h + 1], S[mt][nb][2 * h + 1], v);
                }
                v += __shfl_xor_sync(0xffffffffu, v, 1);
                v += __shfl_xor_sync(0xffffffffu, v, 2);
                if (t4 == 0)
                    red[warpn * 128 + warpm * 32 + mt * 16 + h * 8 + g] = v;
            }
        __syncthreads();

        // PLAIN row-major output: pair j at element offset j.
        __nv_bfloat162* __restrict__ Out =
            (__nv_bfloat162*)(which ? g_KB : g_Q);
#pragma unroll
        for (int mt = 0; mt < 2; mt++)
#pragma unroll
            for (int h = 0; h < 2; h++) {
                int rowl = warpm * 32 + mt * 16 + h * 8 + g;
                float tot = (red[rowl] + red[128 + rowl]) +
                            (red[256 + rowl] + red[384 + rowl]);
                float scale = 1.0f / fmaxf(sqrtf(tot), 1e-12f);
                __nv_bfloat162* orow = Out + (size_t)(row0 + rowl) * 128;
#pragma unroll
                for (int nb = 0; nb < 8; nb++) {
                    int j = warpn * 32 + nb * 4 + t4;
                    orow[j] = __floats2bfloat162_rn(
                        S[mt][nb][2 * h] * scale, S[mt][nb][2 * h + 1] * scale);
                }
            }
        __syncthreads();   // red reads done before next pass writes
    }
}

// ---------------------------------------------------------------------------
// Kernel 2: flash attention partials + fused finalize (last CTA merges).
// Grid (32 qtiles, B, NSPLIT); 2 CTAs co-resident per SM.
// Fragment loads via ldmatrix.x4 on plain row-major tiles.
// NOTE: Q rows hold all 256 d (chunk offset c4*128 bytes); K slot rows hold
// ONLY the current 64-d window (k offset ks*32 bytes, no c4 term).
// ---------------------------------------------------------------------------
#define QST   528
#define KST2  144                            /* 128B data + 16 pad */
#define SLOT2 (128 * KST2)                   /* 18432 */
#define SM_Q   0
#define SM_K   (128 * QST)                   /* 67584 */
#define SM_C   (SM_K + 2 * SLOT2)            /* 104448 */
#define SM_R   SM_K                          /* overlay on dead K slots */
#define SM_TOT (SM_C + KEYS_PER_SPLIT * 8)   /* 112640 */

#define SCALE_EX2 14.4269504088896340f       /* 10 * log2(e) */

__global__ void __launch_bounds__(256, 2)
attn_kernel(const float* __restrict__ coords,
            const float* __restrict__ alpha_p,
            float* __restrict__ out_new,
            float* __restrict__ out_disp) {
    extern __shared__ __align__(1024) char smem[];
    __shared__ int s_last;
    const uint32_t sb = smem_u32(smem);
    const int tid  = threadIdx.x;
    const int lane = tid & 31;
    const int warp = tid >> 5;
    const int warpm = warp & 3, warpn = warp >> 2;
    const int g  = lane >> 2, t4 = lane & 3;
    const int b  = blockIdx.y;
    const int q0 = blockIdx.x * 128;
    const int split = blockIdx.z;

    const __nv_bfloat16* __restrict__ Qg = g_Q + (size_t)(b * L_ + q0) * D_;
    const __nv_bfloat16* __restrict__ KgT =
        g_KB + (size_t)(b * L_ + split * KEYS_PER_SPLIT) * D_;
    const float2* __restrict__ Cg2 = (const float2*)coords + (size_t)b * L_ +
                                     split * KEYS_PER_SPLIT;

    // ldmatrix lane-address bases.
    // A (x4): lanes 0-7 rows m0-7 @k0 | 8-15 rows m8-15 @k0
    //       | 16-23 rows m0-7 @k+8 | 24-31 rows m8-15 @k+8
    const uint32_t qlm = sb + SM_Q +
        (warpm * 32 + (lane & 15)) * QST + (lane >> 4) * 16;
    // B (x4, nb pair): lanes 0-7 keys 8nb @k0 | 8-15 keys 8nb @k+8
    //                | 16-23 keys 8nb+8 @k0 | 24-31 keys 8nb+8 @k+8
    const uint32_t klm =
        (warpn * 64 + ((lane >> 4) << 3) + (lane & 7)) * KST2 +
        ((lane >> 3) & 1) * 16;

    // K-chunk cp.async offsets: 1024 cp16 per 64-d chunk, 4 per thread.
    uint32_t kdst[4];
    int ksrc[4];
#pragma unroll
    for (int i = 0; i < 4; i++) {
        int seg = tid + 256 * i;            // 0..1023; 8 x 16B per key row
        int kr = seg >> 3, ko = (seg & 7) * 16;
        kdst[i] = kr * KST2 + ko;
        ksrc[i] = kr * D_ + ko / 2;         // elements within chunk d-window
    }

    // ---- prologue: Q tile (async) + coords (STS) + chunk 0 (async) ----
#pragma unroll
    for (int i = 0; i < 16; i++) {
        int seg = tid + 256 * i;
        int row = seg >> 5, o = seg & 31;
        cp16(sb + SM_Q + row * QST + o * 16, Qg + row * D_ + o * 8);
    }
    cp_commit();
    ((float4*)(smem + SM_C))[tid]       = ((const float4*)Cg2)[tid];
    ((float4*)(smem + SM_C))[tid + 256] = ((const float4*)Cg2)[tid + 256];
#pragma unroll
    for (int i = 0; i < 4; i++)
        cp16(sb + SM_K + kdst[i], KgT + ksrc[i]);
    cp_commit();

    float l[4], ax[4], ay[4];
#pragma unroll
    for (int s = 0; s < 4; s++) { l[s] = 0.f; ax[s] = 0.f; ay[s] = 0.f; }

    const float4* __restrict__ C4 = (const float4*)(smem + SM_C);

    for (int t = 0; t < TILES_PER_SPLIT; t++) {
        float S[2][8][4];
#pragma unroll
        for (int mt = 0; mt < 2; mt++)
#pragma unroll
            for (int nb = 0; nb < 8; nb++)
#pragma unroll
                for (int r = 0; r < 4; r++) S[mt][nb][r] = 0.f;

        for (int c4 = 0; c4 < 4; c4++) {
            const int c = t * 4 + c4;
            cp_wait0();                     // chunk c landed
            __syncthreads();                // all warps done with chunk c-1
            if (c + 1 < CHUNKS2) {
                int nc = c + 1;
                uint32_t slot = sb + SM_K + (nc & 1) * SLOT2;
                const __nv_bfloat16* src =
                    KgT + (nc >> 2) * (128 * D_) + (nc & 3) * 64;
#pragma unroll
                for (int i = 0; i < 4; i++)
                    cp16(slot + kdst[i], src + ksrc[i]);
                cp_commit();
            }

            const uint32_t slot = sb + SM_K + (c & 1) * SLOT2;
#pragma unroll
            for (int ks = 0; ks < 4; ks++) {
                const int kbase_a = c4 * 128 + ks * 32;  // Q: full-d rows
                const int kbase_b = ks * 32;             // K slot: 64-d rows
                uint32_t a[2][4];
                LDSM_X4(a[0][0], a[0][1], a[0][2], a[0][3], qlm + kbase_a);
                LDSM_X4(a[1][0], a[1][1], a[1][2], a[1][3],
                        qlm + 16 * QST + kbase_a);
#pragma unroll
                for (int nbp = 0; nbp < 4; nbp++) {
                    uint32_t b0, b1, c0, c1;
                    LDSM_X4(b0, b1, c0, c1,
                            slot + klm + nbp * 16 * KST2 + kbase_b);
                    MMA_BF16(S[0][2 * nbp],     a[0][0], a[0][1], a[0][2],
                             a[0][3], b0, b1);
                    MMA_BF16(S[0][2 * nbp + 1], a[0][0], a[0][1], a[0][2],
                             a[0][3], c0, c1);
                    MMA_BF16(S[1][2 * nbp],     a[1][0], a[1][1], a[1][2],
                             a[1][3], b0, b1);
                    MMA_BF16(S[1][2 * nbp + 1], a[1][0], a[1][1], a[1][2],
                             a[1][3], c0, c1);
                }
            }
        }

        // ---- epilogue: p = 2^(s*10*log2e); accumulate l, ax, ay ----
#pragma unroll
        for (int mt = 0; mt < 2; mt++) {
            const int s0 = mt * 2, s1 = mt * 2 + 1;
#pragma unroll
            for (int nb = 0; nb < 8; nb++) {
                float4 cc = C4[t * 64 + warpn * 32 + nb * 4 + t4];
                float p0 = ex2f(S[mt][nb][0] * SCALE_EX2);
                float p1 = ex2f(S[mt][nb][1] * SCALE_EX2);
                float p2 = ex2f(S[mt][nb][2] * SCALE_EX2);
                float p3 = ex2f(S[mt][nb][3] * SCALE_EX2);
                l[s0] += p0 + p1;
                ax[s0] = fmaf(p0, cc.x, ax[s0]); ay[s0] = fmaf(p0, cc.y, ay[s0]);
                ax[s0] = fmaf(p1, cc.z, ax[s0]); ay[s0] = fmaf(p1, cc.w, ay[s0]);
                l[s1] += p2 + p3;
                ax[s1] = fmaf(p2, cc.x, ax[s1]); ay[s1] = fmaf(p2, cc.y, ay[s1]);
                ax[s1] = fmaf(p3, cc.z, ax[s1]); ay[s1] = fmaf(p3, cc.w, ay[s1]);
            }
        }
    }

    // ---- cross-lane + cross-warpn reduction (red overlays K slots) ----
    float4* __restrict__ red = (float4*)(smem + SM_R);
    __syncthreads();                        // K-slot LDS done before overlay
#pragma unroll
    for (int s = 0; s < 4; s++) {
#pragma unroll
        for (int off = 1; off < 4; off <<= 1) {
            l[s]  += __shfl_xor_sync(0xffffffffu, l[s],  off);
            ax[s] += __shfl_xor_sync(0xffffffffu, ax[s], off);
            ay[s] += __shfl_xor_sync(0xffffffffu, ay[s], off);
        }
        if (t4 == 0) {
            int rowl = warpm * 32 + (s >> 1) * 16 + (s & 1) * 8 + g;
            red[warpn * 128 + rowl] = make_float4(l[s], ax[s], ay[s], 0.f);
        }
    }
    __syncthreads();

    if (tid < 128) {
        float4 r0 = red[tid], r1 = red[128 + tid];
        g_part[split][b * L_ + q0 + tid] =
            make_float4(r0.x + r1.x, r0.y + r1.y, r0.z + r1.z, 0.f);
    }
    __threadfence();
    __syncthreads();
    if (tid == 0)
        s_last = atomicAdd(&g_cnt[b * 32 + blockIdx.x], 1);
    __syncthreads();

    // Last-arriving split CTA merges all partials and writes outputs.
    if (s_last == NSPLIT - 1 && tid < 128) {
        int i = b * L_ + q0 + tid;
        float lv = 0.f, axv = 0.f, ayv = 0.f;
#pragma unroll
        for (int sp = 0; sp < NSPLIT; sp++) {
            float4 p = g_part[sp][i];
            lv += p.x; axv += p.y; ayv += p.z;
        }
        float a = 1.0f / (1.0f + __expf(-alpha_p[0]));
        float inv = 1.0f / lv;
        float wx = axv * inv, wy = ayv * inv;
        float2 c = ((const float2*)coords)[i];
        float nx = a * wx + (1.0f - a) * c.x;
        float ny = a * wy + (1.0f - a) * c.y;
        out_new[2 * i + 0]  = nx;
        out_new[2 * i + 1]  = ny;
        out_disp[2 * i + 0] = nx - c.x;
        out_disp[2 * i + 1] = ny - c.y;
    }
}

// ---------------------------------------------------------------------------
// Inputs: latents, current_coords, Wq, Wk, alpha_raw, layer_idx.
// Output: concat(new_coords[B,L,2], displacement[B,L,2]) fp32.
// ---------------------------------------------------------------------------
extern "C" void kernel_launch(void* const* d_in, const int* in_sizes, int n_in,
                              void* d_out, int out_size) {
    const float* latents   = (const float*)d_in[0];
    const float* coords    = (const float*)d_in[1];
    const float* Wq        = (const float*)d_in[2];
    const float* Wk        = (const float*)d_in[3];
    const float* alpha_raw = (const float*)d_in[4];
    float* out = (float*)d_out;

    convert_kernel<<<(2 * WPAIRS) / 256, 256>>>(Wq, Wk);

    cudaFuncSetAttribute(proj_mma_kernel,
                         cudaFuncAttributeMaxDynamicSharedMemorySize, P_TOT);
    proj_mma_kernel<<<BL_ / 128, 512, P_TOT>>>(latents);

    cudaFuncSetAttribute(attn_kernel,
                         cudaFuncAttributeMaxDynamicSharedMemorySize, SM_TOT);
    attn_kernel<<<dim3(L_ / 128, B_, NSPLIT), 256, SM_TOT>>>(
        coords, alpha_raw, out, out + BL_ * 2);
}

// round 14
// speedup vs baseline: 1.4630x; 1.0620x over previous
#include <cuda_runtime.h>
#include <cuda_bf16.h>
#include <math_constants.h>
#include <cstdint>

#define B_  4
#define L_  4096
#define D_  256
#define BL_ (B_ * L_)
#define NSPLIT 4
#define KEYS_PER_SPLIT (L_ / NSPLIT)            /* 1024 */
#define TILES_PER_SPLIT (KEYS_PER_SPLIT / 128)  /* 8 */
#define CHUNKS2 (TILES_PER_SPLIT * 4)           /* 32 x 64-d chunks */

// g_Q / g_KB / g_Wqb / g_Wkb: PLAIN row-major bf16 (ldmatrix layout).
__device__ __align__(1024) __nv_bfloat16 g_Q[BL_ * D_];
__device__ __align__(1024) __nv_bfloat16 g_KB[BL_ * D_];
__device__ __align__(1024) __nv_bfloat16 g_Wqb[D_ * D_];
__device__ __align__(1024) __nv_bfloat16 g_Wkb[D_ * D_];
__device__ __align__(1024) float4 g_part[NSPLIT][BL_];   // (l, ax, ay)
__device__ int g_cnt[B_ * 32];                           // merge counters

// ---------------------------------------------------------------------------
// helpers
// ---------------------------------------------------------------------------
__device__ __forceinline__ uint32_t smem_u32(const void* p) {
    uint32_t a;
    asm("{ .reg .u64 t; cvta.to.shared.u64 t, %1; cvt.u32.u64 %0, t; }"
        : "=r"(a) : "l"(p));
    return a;
}

__device__ __forceinline__ float ex2f(float x) {
    float y;
    asm("ex2.approx.f32 %0, %1;" : "=f"(y) : "f"(x));
    return y;
}

__device__ __forceinline__ void cp16(uint32_t dst, const void* src) {
    asm volatile("cp.async.cg.shared.global [%0], [%1], 16;"
                 :: "r"(dst), "l"(src) : "memory");
}
__device__ __forceinline__ void cp_commit() {
    asm volatile("cp.async.commit_group;" ::: "memory");
}
__device__ __forceinline__ void cp_wait0() {
    asm volatile("cp.async.wait_group 0;" ::: "memory");
}
__device__ __forceinline__ void cp_wait2() {
    asm volatile("cp.async.wait_group 2;" ::: "memory");
}

__device__ __forceinline__ void sts128(uint32_t a, uint32_t r0, uint32_t r1,
                                       uint32_t r2, uint32_t r3) {
    asm volatile("st.shared.v4.b32 [%0], {%1, %2, %3, %4};"
                 :: "r"(a), "r"(r0), "r"(r1), "r"(r2), "r"(r3) : "memory");
}

#define LDSM_X4(r0, r1, r2, r3, addr) \
    asm volatile("ldmatrix.sync.aligned.m8n8.x4.shared.b16 " \
                 "{%0, %1, %2, %3}, [%4];" \
                 : "=r"(r0), "=r"(r1), "=r"(r2), "=r"(r3) : "r"(addr))

#define MMA_BF16(d, a0, a1, a2, a3, b0, b1) \
    asm volatile("mma.sync.aligned.m16n8k16.row.col.f32.bf16.bf16.f32 " \
                 "{%0,%1,%2,%3},{%4,%5,%6,%7},{%8,%9},{%0,%1,%2,%3};" \
                 : "+f"((d)[0]), "+f"((d)[1]), "+f"((d)[2]), "+f"((d)[3]) \
                 : "r"(a0), "r"(a1), "r"(a2), "r"(a3), "r"(b0), "r"(b1))

__device__ __forceinline__ uint32_t bf2(float lo, float hi) {
    __nv_bfloat162 v = __floats2bfloat162_rn(lo, hi);
    return *(uint32_t*)&v;
}

// ---------------------------------------------------------------------------
// Kernel 0: round Wq / Wk to bf16 plain row-major; zero merge counters.
// ---------------------------------------------------------------------------
#define WPAIRS (D_ * 128)

__global__ void __launch_bounds__(256)
convert_kernel(const float* __restrict__ Wq, const float* __restrict__ Wk) {
    int idx = blockIdx.x * 256 + threadIdx.x;     // 0 .. 2*WPAIRS-1
    if (idx < B_ * 32) g_cnt[idx] = 0;
    const float* src = (idx < WPAIRS) ? Wq : Wk;
    __nv_bfloat162* dst = (__nv_bfloat162*)((idx < WPAIRS) ? g_Wqb : g_Wkb);
    int i = (idx < WPAIRS) ? idx : idx - WPAIRS;
    float2 v = __ldg((const float2*)src + i);
    dst[i] = __floats2bfloat162_rn(v.x, v.y);
}

// ---------------------------------------------------------------------------
// Kernel 1: proj via mma.sync bf16 + ldmatrix. One CTA = 128 rows x BOTH
// Wq and Wk (X tile resident; 16-chunk W stream = 8 Wq + 8 Wk, 32-d each).
// X read fp32 directly from latents (LDG -> bf16 pack -> plain STS).
// Row L2-norm fused; output PLAIN row-major to g_Q / g_KB.
// 512 threads = 16 warps (warpm 0..3 x warpn 0..3), warp tile 32m x 64n.
// NOTE: X rows hold all 256 d (kbase_a = (gc&7)*64 + ks*32 bytes); W slot
// rows hold ONLY the 32-d chunk window (kbase_b = ks*32 bytes).
// ---------------------------------------------------------------------------
#define PXST 528                             /* X row bytes (512 + 16) */
#define PWST 80                              /* W row bytes (64 + 16) */
#define P_SLOT (D_ * PWST)                   /* 20480 */
#define P_SMX 0
#define P_SMW (128 * PXST)                   /* 67584 */
#define P_RED (P_SMW + 4 * P_SLOT)           /* 149504 */
#define P_TOT (P_RED + 2048)                 /* 151552 */

__global__ void __launch_bounds__(512, 1)
proj_mma_kernel(const float* __restrict__ latents) {
    extern __shared__ __align__(1024) char smem[];
    const uint32_t sb = smem_u32(smem);
    const int tid  = threadIdx.x;
    const int lane = tid & 31;
    const int warp = tid >> 5;
    const int warpm = warp & 3, warpn = warp >> 2;   // 4 x 4
    const int g  = lane >> 2, t4 = lane & 3;
    const int row0 = blockIdx.x * 128;

    // ldmatrix lane-address bases (same scheme as attn).
    const uint32_t qlm = sb + P_SMX +
        (warpm * 32 + (lane & 15)) * PXST + (lane >> 4) * 16;
    const uint32_t klm =
        (warpn * 64 + ((lane >> 4) << 3) + (lane & 7)) * PWST +
        ((lane >> 3) & 1) * 16;

    // W-chunk cp.async offsets: 1024 cp16 per chunk, 2 per thread.
    const int wn0 = tid >> 2,           wo0 = (tid & 3) * 16;
    const int wn1 = (tid + 512) >> 2,   wo1 = ((tid + 512) & 3) * 16;
    const uint32_t wd0 = wn0 * PWST + wo0, wd1 = wn1 * PWST + wo1;
    const int ws0 = wn0 * D_ + wo0 / 2, ws1 = wn1 * D_ + wo1 / 2;

    // ---- prologue: first 3 W chunks (async) + X fp32->bf16 plain STS ----
#pragma unroll
    for (int gc = 0; gc < 3; gc++) {
        uint32_t slot = sb + P_SMW + (gc & 3) * P_SLOT;
        const __nv_bfloat16* src = g_Wqb + gc * 32;
        cp16(slot + wd0, src + ws0);
        cp16(slot + wd1, src + ws1);
        cp_commit();
    }
    {
        const float4* __restrict__ Xf4 =
            (const float4*)(latents + (size_t)row0 * D_);
#pragma unroll
        for (int i = 0; i < 4; i++) {
            int idx = tid + 512 * i;            // 0..2047
            int r = idx >> 4, gg = idx & 15;    // row, 16-d group
            const float4* p = Xf4 + r * 64 + gg * 4;
            float4 v0 = __ldg(p + 0), v1 = __ldg(p + 1);
            float4 v2 = __ldg(p + 2), v3 = __ldg(p + 3);
            uint32_t sa = sb + P_SMX + r * PXST + gg * 32;
            sts128(sa,      bf2(v0.x, v0.y), bf2(v0.z, v0.w),
                            bf2(v1.x, v1.y), bf2(v1.z, v1.w));
            sts128(sa + 16, bf2(v2.x, v2.y), bf2(v2.z, v2.w),
                            bf2(v3.x, v3.y), bf2(v3.z, v3.w));
        }
    }

    float* __restrict__ red = (float*)(smem + P_RED);

    for (int which = 0; which < 2; which++) {
        float S[2][8][4];
#pragma unroll
        for (int mt = 0; mt < 2; mt++)
#pragma unroll
            for (int nb = 0; nb < 8; nb++)
#pragma unroll
                for (int r = 0; r < 4; r++) S[mt][nb][r] = 0.f;

        for (int c8 = 0; c8 < 8; c8++) {
            const int gc = which * 8 + c8;
            cp_wait2();
            __syncthreads();
            if (gc + 3 < 16) {
                int nc = gc + 3;
                uint32_t slot = sb + P_SMW + (nc & 3) * P_SLOT;
                const __nv_bfloat16* src =
                    (nc < 8 ? g_Wqb : g_Wkb) + (nc & 7) * 32;
                cp16(slot + wd0, src + ws0);
                cp16(slot + wd1, src + ws1);
            }
            cp_commit();

            const uint32_t slot = sb + P_SMW + (gc & 3) * P_SLOT;
#pragma unroll
            for (int ks = 0; ks < 2; ks++) {
                const int kbase_a = c8 * 64 + ks * 32;   // X: full-d rows
                const int kbase_b = ks * 32;             // W slot: 32-d rows
                uint32_t a[2][4];
                LDSM_X4(a[0][0], a[0][1], a[0][2], a[0][3], qlm + kbase_a);
                LDSM_X4(a[1][0], a[1][1], a[1][2], a[1][3],
                        qlm + 16 * PXST + kbase_a);
#pragma unroll
                for (int nbp = 0; nbp < 4; nbp++) {
                    uint32_t b0, b1, c0, c1;
                    LDSM_X4(b0, b1, c0, c1,
                            slot + klm + nbp * 16 * PWST + kbase_b);
                    MMA_BF16(S[0][2 * nbp],     a[0][0], a[0][1], a[0][2],
                             a[0][3], b0, b1);
                    MMA_BF16(S[0][2 * nbp + 1], a[0][0], a[0][1], a[0][2],
                             a[0][3], c0, c1);
                    MMA_BF16(S[1][2 * nbp],     a[1][0], a[1][1], a[1][2],
                             a[1][3], b0, b1);
                    MMA_BF16(S[1][2 * nbp + 1], a[1][0], a[1][1], a[1][2],
                             a[1][3], c0, c1);
                }
            }
        }

        // ---- row sum-of-squares: quad shfl + cross-warpn exchange ----
        __syncthreads();   // last chunk's loads done before red reuse below
#pragma unroll
        for (int mt = 0; mt < 2; mt++)
#pragma unroll
            for (int h = 0; h < 2; h++) {
                float v = 0.f;
#pragma unroll
                for (int nb = 0; nb < 8; nb++) {
                    v = fmaf(S[mt][nb][2 * h], S[mt][nb][2 * h], v);
                    v = fmaf(S[mt][nb][2 * h + 1], S[mt][nb][2 * h + 1], v);
                }
                v += __shfl_xor_sync(0xffffffffu, v, 1);
                v += __shfl_xor_sync(0xffffffffu, v, 2);
                if (t4 == 0)
                    red[warpn * 128 + warpm * 32 + mt * 16 + h * 8 + g] = v;
            }
        __syncthreads();

        // PLAIN row-major output: S[mt][nb] covers cols warpn*64+nb*8+2t4(+1)
        // -> pair index j = warpn*32 + nb*4 + t4.
        __nv_bfloat162* __restrict__ Out =
            (__nv_bfloat162*)(which ? g_KB : g_Q);
#pragma unroll
        for (int mt = 0; mt < 2; mt++)
#pragma unroll
            for (int h = 0; h < 2; h++) {
                int rowl = warpm * 32 + mt * 16 + h * 8 + g;
                float tot = (red[rowl] + red[128 + rowl]) +
                            (red[256 + rowl] + red[384 + rowl]);
                float scale = 1.0f / fmaxf(sqrtf(tot), 1e-12f);
                __nv_bfloat162* orow = Out + (size_t)(row0 + rowl) * 128;
#pragma unroll
                for (int nb = 0; nb < 8; nb++) {
                    int j = warpn * 32 + nb * 4 + t4;
                    orow[j] = __floats2bfloat162_rn(
                        S[mt][nb][2 * h] * scale, S[mt][nb][2 * h + 1] * scale);
                }
            }
        __syncthreads();   // red reads done before next pass writes
    }
}

// ---------------------------------------------------------------------------
// Kernel 2: flash attention partials + fused finalize (last CTA merges).
// Grid (32 qtiles, B, NSPLIT); 2 CTAs co-resident per SM.
// Fragment loads via ldmatrix.x4 on plain row-major tiles.
// NOTE: Q rows hold all 256 d (chunk offset c4*128 bytes); K slot rows hold
// ONLY the current 64-d window (k offset ks*32 bytes, no c4 term).
// ---------------------------------------------------------------------------
#define QST   528
#define KST2  144                            /* 128B data + 16 pad */
#define SLOT2 (128 * KST2)                   /* 18432 */
#define SM_Q   0
#define SM_K   (128 * QST)                   /* 67584 */
#define SM_C   (SM_K + 2 * SLOT2)            /* 104448 */
#define SM_R   SM_K                          /* overlay on dead K slots */
#define SM_TOT (SM_C + KEYS_PER_SPLIT * 8)   /* 112640 */

#define SCALE_EX2 14.4269504088896340f       /* 10 * log2(e) */

__global__ void __launch_bounds__(256, 2)
attn_kernel(const float* __restrict__ coords,
            const float* __restrict__ alpha_p,
            float* __restrict__ out_new,
            float* __restrict__ out_disp) {
    extern __shared__ __align__(1024) char smem[];
    __shared__ int s_last;
    const uint32_t sb = smem_u32(smem);
    const int tid  = threadIdx.x;
    const int lane = tid & 31;
    const int warp = tid >> 5;
    const int warpm = warp & 3, warpn = warp >> 2;
    const int g  = lane >> 2, t4 = lane & 3;
    const int b  = blockIdx.y;
    const int q0 = blockIdx.x * 128;
    const int split = blockIdx.z;

    const __nv_bfloat16* __restrict__ Qg = g_Q + (size_t)(b * L_ + q0) * D_;
    const __nv_bfloat16* __restrict__ KgT =
        g_KB + (size_t)(b * L_ + split * KEYS_PER_SPLIT) * D_;
    const float2* __restrict__ Cg2 = (const float2*)coords + (size_t)b * L_ +
                                     split * KEYS_PER_SPLIT;

    // ldmatrix lane-address bases.
    const uint32_t qlm = sb + SM_Q +
        (warpm * 32 + (lane & 15)) * QST + (lane >> 4) * 16;
    const uint32_t klm =
        (warpn * 64 + ((lane >> 4) << 3) + (lane & 7)) * KST2 +
        ((lane >> 3) & 1) * 16;

    // K-chunk cp.async offsets: 1024 cp16 per 64-d chunk, 4 per thread.
    uint32_t kdst[4];
    int ksrc[4];
#pragma unroll
    for (int i = 0; i < 4; i++) {
        int seg = tid + 256 * i;            // 0..1023; 8 x 16B per key row
        int kr = seg >> 3, ko = (seg & 7) * 16;
        kdst[i] = kr * KST2 + ko;
        ksrc[i] = kr * D_ + ko / 2;         // elements within chunk d-window
    }

    // ---- prologue: Q tile (async) + coords (STS) + chunk 0 (async) ----
#pragma unroll
    for (int i = 0; i < 16; i++) {
        int seg = tid + 256 * i;
        int row = seg >> 5, o = seg & 31;
        cp16(sb + SM_Q + row * QST + o * 16, Qg + row * D_ + o * 8);
    }
    cp_commit();
    ((float4*)(smem + SM_C))[tid]       = ((const float4*)Cg2)[tid];
    ((float4*)(smem + SM_C))[tid + 256] = ((const float4*)Cg2)[tid + 256];
#pragma unroll
    for (int i = 0; i < 4; i++)
        cp16(sb + SM_K + kdst[i], KgT + ksrc[i]);
    cp_commit();

    float l[4], ax[4], ay[4];
#pragma unroll
    for (int s = 0; s < 4; s++) { l[s] = 0.f; ax[s] = 0.f; ay[s] = 0.f; }

    const float4* __restrict__ C4 = (const float4*)(smem + SM_C);

    for (int t = 0; t < TILES_PER_SPLIT; t++) {
        float S[2][8][4];
#pragma unroll
        for (int mt = 0; mt < 2; mt++)
#pragma unroll
            for (int nb = 0; nb < 8; nb++)
#pragma unroll
                for (int r = 0; r < 4; r++) S[mt][nb][r] = 0.f;

        for (int c4 = 0; c4 < 4; c4++) {
            const int c = t * 4 + c4;
            cp_wait0();                     // chunk c landed
            __syncthreads();                // all warps done with chunk c-1
            if (c + 1 < CHUNKS2) {
                int nc = c + 1;
                uint32_t slot = sb + SM_K + (nc & 1) * SLOT2;
                const __nv_bfloat16* src =
                    KgT + (nc >> 2) * (128 * D_) + (nc & 3) * 64;
#pragma unroll
                for (int i = 0; i < 4; i++)
                    cp16(slot + kdst[i], src + ksrc[i]);
                cp_commit();
            }

            const uint32_t slot = sb + SM_K + (c & 1) * SLOT2;
#pragma unroll
            for (int ks = 0; ks < 4; ks++) {
                const int kbase_a = c4 * 128 + ks * 32;  // Q: full-d rows
                const int kbase_b = ks * 32;             // K slot: 64-d rows
                uint32_t a[2][4];
                LDSM_X4(a[0][0], a[0][1], a[0][2], a[0][3], qlm + kbase_a);
                LDSM_X4(a[1][0], a[1][1], a[1][2], a[1][3],
                        qlm + 16 * QST + kbase_a);
#pragma unroll
                for (int nbp = 0; nbp < 4; nbp++) {
                    uint32_t b0, b1, c0, c1;
                    LDSM_X4(b0, b1, c0, c1,
                            slot + klm + nbp * 16 * KST2 + kbase_b);
                    MMA_BF16(S[0][2 * nbp],     a[0][0], a[0][1], a[0][2],
                             a[0][3], b0, b1);
                    MMA_BF16(S[0][2 * nbp + 1], a[0][0], a[0][1], a[0][2],
                             a[0][3], c0, c1);
                    MMA_BF16(S[1][2 * nbp],     a[1][0], a[1][1], a[1][2],
                             a[1][3], b0, b1);
                    MMA_BF16(S[1][2 * nbp + 1], a[1][0], a[1][1], a[1][2],
                             a[1][3], c0, c1);
                }
            }
        }

        // ---- epilogue: p = 2^(s*10*log2e); accumulate l, ax, ay ----
#pragma unroll
        for (int mt = 0; mt < 2; mt++) {
            const int s0 = mt * 2, s1 = mt * 2 + 1;
#pragma unroll
            for (int nb = 0; nb < 8; nb++) {
                float4 cc = C4[t * 64 + warpn * 32 + nb * 4 + t4];
                float p0 = ex2f(S[mt][nb][0] * SCALE_EX2);
                float p1 = ex2f(S[mt][nb][1] * SCALE_EX2);
                float p2 = ex2f(S[mt][nb][2] * SCALE_EX2);
                float p3 = ex2f(S[mt][nb][3] * SCALE_EX2);
                l[s0] += p0 + p1;
                ax[s0] = fmaf(p0, cc.x, ax[s0]); ay[s0] = fmaf(p0, cc.y, ay[s0]);
                ax[s0] = fmaf(p1, cc.z, ax[s0]); ay[s0] = fmaf(p1, cc.w, ay[s0]);
                l[s1] += p2 + p3;
                ax[s1] = fmaf(p2, cc.x, ax[s1]); ay[s1] = fmaf(p2, cc.y, ay[s1]);
                ax[s1] = fmaf(p3, cc.z, ax[s1]); ay[s1] = fmaf(p3, cc.w, ay[s1]);
            }
        }
    }

    // ---- cross-lane + cross-warpn reduction (red overlays K slots) ----
    float4* __restrict__ red = (float4*)(smem + SM_R);
    __syncthreads();                        // K-slot loads done before overlay
#pragma unroll
    for (int s = 0; s < 4; s++) {
#pragma unroll
        for (int off = 1; off < 4; off <<= 1) {
            l[s]  += __shfl_xor_sync(0xffffffffu, l[s],  off);
            ax[s] += __shfl_xor_sync(0xffffffffu, ax[s], off);
            ay[s] += __shfl_xor_sync(0xffffffffu, ay[s], off);
        }
        if (t4 == 0) {
            int rowl = warpm * 32 + (s >> 1) * 16 + (s & 1) * 8 + g;
            red[warpn * 128 + rowl] = make_float4(l[s], ax[s], ay[s], 0.f);
        }
    }
    __syncthreads();

    if (tid < 128) {
        float4 r0 = red[tid], r1 = red[128 + tid];
        g_part[split][b * L_ + q0 + tid] =
            make_float4(r0.x + r1.x, r0.y + r1.y, r0.z + r1.z, 0.f);
    }
    __threadfence();
    __syncthreads();
    if (tid == 0)
        s_last = atomicAdd(&g_cnt[b * 32 + blockIdx.x], 1);
    __syncthreads();

    // Last-arriving split CTA merges all partials and writes outputs.
    if (s_last == NSPLIT - 1 && tid < 128) {
        int i = b * L_ + q0 + tid;
        float lv = 0.f, axv = 0.f, ayv = 0.f;
#pragma unroll
        for (int sp = 0; sp < NSPLIT; sp++) {
            float4 p = g_part[sp][i];
            lv += p.x; axv += p.y; ayv += p.z;
        }
        float a = 1.0f / (1.0f + __expf(-alpha_p[0]));
        float inv = 1.0f / lv;
        float wx = axv * inv, wy = ayv * inv;
        float2 c = ((const float2*)coords)[i];
        float nx = a * wx + (1.0f - a) * c.x;
        float ny = a * wy + (1.0f - a) * c.y;
        out_new[2 * i + 0]  = nx;
        out_new[2 * i + 1]  = ny;
        out_disp[2 * i + 0] = nx - c.x;
        out_disp[2 * i + 1] = ny - c.y;
    }
}

// ---------------------------------------------------------------------------
// Inputs: latents, current_coords, Wq, Wk, alpha_raw, layer_idx.
// Output: concat(new_coords[B,L,2], displacement[B,L,2]) fp32.
// ---------------------------------------------------------------------------
extern "C" void kernel_launch(void* const* d_in, const int* in_sizes, int n_in,
                              void* d_out, int out_size) {
    const float* latents   = (const float*)d_in[0];
    const float* coords    = (const float*)d_in[1];
    const float* Wq        = (const float*)d_in[2];
    const float* Wk        = (const float*)d_in[3];
    const float* alpha_raw = (const float*)d_in[4];
    float* out = (float*)d_out;

    convert_kernel<<<(2 * WPAIRS) / 256, 256>>>(Wq, Wk);

    cudaFuncSetAttribute(proj_mma_kernel,
                         cudaFuncAttributeMaxDynamicSharedMemorySize, P_TOT);
    proj_mma_kernel<<<BL_ / 128, 512, P_TOT>>>(latents);

    cudaFuncSetAttribute(attn_kernel,
                         cudaFuncAttributeMaxDynamicSharedMemorySize, SM_TOT);
    attn_kernel<<<dim3(L_ / 128, B_, NSPLIT), 256, SM_TOT>>>(
        coords, alpha_raw, out, out + BL_ * 2);
}

// round 15
// speedup vs baseline: 1.5398x; 1.0525x over previous
#include <cuda_runtime.h>
#include <cuda_bf16.h>
#include <math_constants.h>
#include <cstdint>

#define B_  4
#define L_  4096
#define D_  256
#define BL_ (B_ * L_)
#define NSPLIT 4
#define KEYS_PER_SPLIT (L_ / NSPLIT)            /* 1024 */
#define TILES_PER_SPLIT (KEYS_PER_SPLIT / 128)  /* 8 */
#define CHUNKS2 (TILES_PER_SPLIT * 4)           /* 32 x 64-d chunks */

// g_Q / g_KB / g_Wqb / g_Wkb: PLAIN row-major bf16 (ldmatrix layout).
__device__ __align__(1024) __nv_bfloat16 g_Q[BL_ * D_];
__device__ __align__(1024) __nv_bfloat16 g_KB[BL_ * D_];
__device__ __align__(1024) __nv_bfloat16 g_Wqb[D_ * D_];
__device__ __align__(1024) __nv_bfloat16 g_Wkb[D_ * D_];
__device__ __align__(1024) float4 g_part[NSPLIT][BL_];   // (l, ax, ay)
__device__ int g_cnt[B_ * 32];                           // merge counters

// ---------------------------------------------------------------------------
// helpers
// ---------------------------------------------------------------------------
__device__ __forceinline__ uint32_t smem_u32(const void* p) {
    uint32_t a;
    asm("{ .reg .u64 t; cvta.to.shared.u64 t, %1; cvt.u32.u64 %0, t; }"
        : "=r"(a) : "l"(p));
    return a;
}

__device__ __forceinline__ float ex2f(float x) {
    float y;
    asm("ex2.approx.f32 %0, %1;" : "=f"(y) : "f"(x));
    return y;
}

__device__ __forceinline__ void cp16(uint32_t dst, const void* src) {
    asm volatile("cp.async.cg.shared.global [%0], [%1], 16;"
                 :: "r"(dst), "l"(src) : "memory");
}
__device__ __forceinline__ void cp_commit() {
    asm volatile("cp.async.commit_group;" ::: "memory");
}
__device__ __forceinline__ void cp_wait0() {
    asm volatile("cp.async.wait_group 0;" ::: "memory");
}
__device__ __forceinline__ void cp_wait2() {
    asm volatile("cp.async.wait_group 2;" ::: "memory");
}

__device__ __forceinline__ void sts128(uint32_t a, uint32_t r0, uint32_t r1,
                                       uint32_t r2, uint32_t r3) {
    asm volatile("st.shared.v4.b32 [%0], {%1, %2, %3, %4};"
                 :: "r"(a), "r"(r0), "r"(r1), "r"(r2), "r"(r3) : "memory");
}

#define LDSM_X4(r0, r1, r2, r3, addr) \
    asm volatile("ldmatrix.sync.aligned.m8n8.x4.shared.b16 " \
                 "{%0, %1, %2, %3}, [%4];" \
                 : "=r"(r0), "=r"(r1), "=r"(r2), "=r"(r3) : "r"(addr))

#define LDSM_X2_TRANS(r0, r1, addr) \
    asm volatile("ldmatrix.sync.aligned.m8n8.x2.trans.shared.b16 " \
                 "{%0, %1}, [%2];" \
                 : "=r"(r0), "=r"(r1) : "r"(addr))

#define MMA_BF16(d, a0, a1, a2, a3, b0, b1) \
    asm volatile("mma.sync.aligned.m16n8k16.row.col.f32.bf16.bf16.f32 " \
                 "{%0,%1,%2,%3},{%4,%5,%6,%7},{%8,%9},{%0,%1,%2,%3};" \
                 : "+f"((d)[0]), "+f"((d)[1]), "+f"((d)[2]), "+f"((d)[3]) \
                 : "r"(a0), "r"(a1), "r"(a2), "r"(a3), "r"(b0), "r"(b1))

__device__ __forceinline__ uint32_t bf2(float lo, float hi) {
    __nv_bfloat162 v = __floats2bfloat162_rn(lo, hi);
    return *(uint32_t*)&v;
}

// ---------------------------------------------------------------------------
// Kernel 0: round Wq / Wk to bf16 plain row-major; zero merge counters.
// ---------------------------------------------------------------------------
#define WPAIRS (D_ * 128)

__global__ void __launch_bounds__(256)
convert_kernel(const float* __restrict__ Wq, const float* __restrict__ Wk) {
    int idx = blockIdx.x * 256 + threadIdx.x;     // 0 .. 2*WPAIRS-1
    if (idx < B_ * 32) g_cnt[idx] = 0;
    const float* src = (idx < WPAIRS) ? Wq : Wk;
    __nv_bfloat162* dst = (__nv_bfloat162*)((idx < WPAIRS) ? g_Wqb : g_Wkb);
    int i = (idx < WPAIRS) ? idx : idx - WPAIRS;
    float2 v = __ldg((const float2*)src + i);
    dst[i] = __floats2bfloat162_rn(v.x, v.y);
}

// ---------------------------------------------------------------------------
// Kernel 1: proj via mma.sync bf16 + ldmatrix. One CTA = 128 rows x BOTH
// Wq and Wk (X tile resident; 16-chunk W stream = 8 Wq + 8 Wk, 32-d each).
// X read fp32 directly from latents (LDG -> bf16 pack -> plain STS).
// Row L2-norm fused; output PLAIN row-major to g_Q / g_KB.
// 512 threads = 16 warps (warpm 0..3 x warpn 0..3), warp tile 32m x 64n.
// ---------------------------------------------------------------------------
#define PXST 528                             /* X row bytes (512 + 16) */
#define PWST 80                              /* W row bytes (64 + 16) */
#define P_SLOT (D_ * PWST)                   /* 20480 */
#define P_SMX 0
#define P_SMW (128 * PXST)                   /* 67584 */
#define P_RED (P_SMW + 4 * P_SLOT)           /* 149504 */
#define P_TOT (P_RED + 2048)                 /* 151552 */

__global__ void __launch_bounds__(512, 1)
proj_mma_kernel(const float* __restrict__ latents) {
    extern __shared__ __align__(1024) char smem[];
    const uint32_t sb = smem_u32(smem);
    const int tid  = threadIdx.x;
    const int lane = tid & 31;
    const int warp = tid >> 5;
    const int warpm = warp & 3, warpn = warp >> 2;   // 4 x 4
    const int g  = lane >> 2, t4 = lane & 3;
    const int row0 = blockIdx.x * 128;

    // ldmatrix lane-address bases (same scheme as attn).
    const uint32_t qlm = sb + P_SMX +
        (warpm * 32 + (lane & 15)) * PXST + (lane >> 4) * 16;
    const uint32_t klm =
        (warpn * 64 + ((lane >> 4) << 3) + (lane & 7)) * PWST +
        ((lane >> 3) & 1) * 16;

    // W-chunk cp.async offsets: 1024 cp16 per chunk, 2 per thread.
    const int wn0 = tid >> 2,           wo0 = (tid & 3) * 16;
    const int wn1 = (tid + 512) >> 2,   wo1 = ((tid + 512) & 3) * 16;
    const uint32_t wd0 = wn0 * PWST + wo0, wd1 = wn1 * PWST + wo1;
    const int ws0 = wn0 * D_ + wo0 / 2, ws1 = wn1 * D_ + wo1 / 2;

    // ---- prologue: first 3 W chunks (async) + X fp32->bf16 plain STS ----
#pragma unroll
    for (int gc = 0; gc < 3; gc++) {
        uint32_t slot = sb + P_SMW + (gc & 3) * P_SLOT;
        const __nv_bfloat16* src = g_Wqb + gc * 32;
        cp16(slot + wd0, src + ws0);
        cp16(slot + wd1, src + ws1);
        cp_commit();
    }
    {
        const float4* __restrict__ Xf4 =
            (const float4*)(latents + (size_t)row0 * D_);
#pragma unroll
        for (int i = 0; i < 4; i++) {
            int idx = tid + 512 * i;            // 0..2047
            int r = idx >> 4, gg = idx & 15;    // row, 16-d group
            const float4* p = Xf4 + r * 64 + gg * 4;
            float4 v0 = __ldg(p + 0), v1 = __ldg(p + 1);
            float4 v2 = __ldg(p + 2), v3 = __ldg(p + 3);
            uint32_t sa = sb + P_SMX + r * PXST + gg * 32;
            sts128(sa,      bf2(v0.x, v0.y), bf2(v0.z, v0.w),
                            bf2(v1.x, v1.y), bf2(v1.z, v1.w));
            sts128(sa + 16, bf2(v2.x, v2.y), bf2(v2.z, v2.w),
                            bf2(v3.x, v3.y), bf2(v3.z, v3.w));
        }
    }

    float* __restrict__ red = (float*)(smem + P_RED);

    for (int which = 0; which < 2; which++) {
        float S[2][8][4];
#pragma unroll
        for (int mt = 0; mt < 2; mt++)
#pragma unroll
            for (int nb = 0; nb < 8; nb++)
#pragma unroll
                for (int r = 0; r < 4; r++) S[mt][nb][r] = 0.f;

        for (int c8 = 0; c8 < 8; c8++) {
            const int gc = which * 8 + c8;
            cp_wait2();
            __syncthreads();
            if (gc + 3 < 16) {
                int nc = gc + 3;
                uint32_t slot = sb + P_SMW + (nc & 3) * P_SLOT;
                const __nv_bfloat16* src =
                    (nc < 8 ? g_Wqb : g_Wkb) + (nc & 7) * 32;
                cp16(slot + wd0, src + ws0);
                cp16(slot + wd1, src + ws1);
            }
            cp_commit();

            const uint32_t slot = sb + P_SMW + (gc & 3) * P_SLOT;
#pragma unroll
            for (int ks = 0; ks < 2; ks++) {
                const int kbase_a = c8 * 64 + ks * 32;   // X: full-d rows
                const int kbase_b = ks * 32;             // W slot: 32-d rows
                uint32_t a[2][4];
                LDSM_X4(a[0][0], a[0][1], a[0][2], a[0][3], qlm + kbase_a);
                LDSM_X4(a[1][0], a[1][1], a[1][2], a[1][3],
                        qlm + 16 * PXST + kbase_a);
#pragma unroll
                for (int nbp = 0; nbp < 4; nbp++) {
                    uint32_t b0, b1, c0, c1;
                    LDSM_X4(b0, b1, c0, c1,
                            slot + klm + nbp * 16 * PWST + kbase_b);
                    MMA_BF16(S[0][2 * nbp],     a[0][0], a[0][1], a[0][2],
                             a[0][3], b0, b1);
                    MMA_BF16(S[0][2 * nbp + 1], a[0][0], a[0][1], a[0][2],
                             a[0][3], c0, c1);
                    MMA_BF16(S[1][2 * nbp],     a[1][0], a[1][1], a[1][2],
                             a[1][3], b0, b1);
                    MMA_BF16(S[1][2 * nbp + 1], a[1][0], a[1][1], a[1][2],
                             a[1][3], c0, c1);
                }
            }
        }

        // ---- row sum-of-squares: quad shfl + cross-warpn exchange ----
        __syncthreads();   // last chunk's loads done before red reuse below
#pragma unroll
        for (int mt = 0; mt < 2; mt++)
#pragma unroll
            for (int h = 0; h < 2; h++) {
                float v = 0.f;
#pragma unroll
                for (int nb = 0; nb < 8; nb++) {
                    v = fmaf(S[mt][nb][2 * h], S[mt][nb][2 * h], v);
                    v = fmaf(S[mt][nb][2 * h + 1], S[mt][nb][2 * h + 1], v);
                }
                v += __shfl_xor_sync(0xffffffffu, v, 1);
                v += __shfl_xor_sync(0xffffffffu, v, 2);
                if (t4 == 0)
                    red[warpn * 128 + warpm * 32 + mt * 16 + h * 8 + g] = v;
            }
        __syncthreads();

        // PLAIN row-major output: S[mt][nb] covers cols warpn*64+nb*8+2t4(+1)
        // -> pair index j = warpn*32 + nb*4 + t4.
        __nv_bfloat162* __restrict__ Out =
            (__nv_bfloat162*)(which ? g_KB : g_Q);
#pragma unroll
        for (int mt = 0; mt < 2; mt++)
#pragma unroll
            for (int h = 0; h < 2; h++) {
                int rowl = warpm * 32 + mt * 16 + h * 8 + g;
                float tot = (red[rowl] + red[128 + rowl]) +
                            (red[256 + rowl] + red[384 + rowl]);
                float scale = 1.0f / fmaxf(sqrtf(tot), 1e-12f);
                __nv_bfloat162* orow = Out + (size_t)(row0 + rowl) * 128;
#pragma unroll
                for (int nb = 0; nb < 8; nb++) {
                    int j = warpn * 32 + nb * 4 + t4;
                    orow[j] = __floats2bfloat162_rn(
                        S[mt][nb][2 * h] * scale, S[mt][nb][2 * h + 1] * scale);
                }
            }
        __syncthreads();   // red reads done before next pass writes
    }
}

// ---------------------------------------------------------------------------
// Kernel 2: flash attention partials + fused finalize (last CTA merges).
// Grid (32 qtiles, B, NSPLIT); 2 CTAs co-resident per SM.
// QK fragments via ldmatrix.x4. The P@[coords,1] contraction ALSO runs on
// the tensor pipe: S C-fragments re-pack directly as A-fragments (FA2 layout
// identity), V = [x, y, 1, 0...] bf16 tile (128 x 8, 16B rows) staged in
// SMEM per key-tile, B-fragments via ldmatrix.x2.trans.
// O[mt] accumulates (ax, ay, l) across tiles in fp32.
// ---------------------------------------------------------------------------
#define QST   528
#define KST2  144                            /* 128B data + 16 pad */
#define SLOT2 (128 * KST2)                   /* 18432 */
#define SM_Q   0
#define SM_K   (128 * QST)                   /* 67584 */
#define SM_V   (SM_K + 2 * SLOT2)            /* 104448 */
#define SM_R   SM_K                          /* overlay on dead K slots */
#define SM_TOT (SM_V + 2048)                 /* 106496 */

#define SCALE_EX2 14.4269504088896340f       /* 10 * log2(e) */

__global__ void __launch_bounds__(256, 2)
attn_kernel(const float* __restrict__ coords,
            const float* __restrict__ alpha_p,
            float* __restrict__ out_new,
            float* __restrict__ out_disp) {
    extern __shared__ __align__(1024) char smem[];
    __shared__ int s_last;
    const uint32_t sb = smem_u32(smem);
    const int tid  = threadIdx.x;
    const int lane = tid & 31;
    const int warp = tid >> 5;
    const int warpm = warp & 3, warpn = warp >> 2;
    const int g  = lane >> 2, t4 = lane & 3;
    const int b  = blockIdx.y;
    const int q0 = blockIdx.x * 128;
    const int split = blockIdx.z;

    const __nv_bfloat16* __restrict__ Qg = g_Q + (size_t)(b * L_ + q0) * D_;
    const __nv_bfloat16* __restrict__ KgT =
        g_KB + (size_t)(b * L_ + split * KEYS_PER_SPLIT) * D_;
    const float2* __restrict__ Cg2 = (const float2*)coords + (size_t)b * L_ +
                                     split * KEYS_PER_SPLIT;

    // ldmatrix lane-address bases.
    const uint32_t qlm = sb + SM_Q +
        (warpm * 32 + (lane & 15)) * QST + (lane >> 4) * 16;
    const uint32_t klm =
        (warpn * 64 + ((lane >> 4) << 3) + (lane & 7)) * KST2 +
        ((lane >> 3) & 1) * 16;
    // V tile (128 x 8 bf16, 16B rows): lanes 0-15 supply key-row addresses.
    const uint32_t vlm = sb + SM_V + (warpn * 64 + (lane & 15)) * 16;

    // K-chunk cp.async offsets: 1024 cp16 per 64-d chunk, 4 per thread.
    uint32_t kdst[4];
    int ksrc[4];
#pragma unroll
    for (int i = 0; i < 4; i++) {
        int seg = tid + 256 * i;            // 0..1023; 8 x 16B per key row
        int kr = seg >> 3, ko = (seg & 7) * 16;
        kdst[i] = kr * KST2 + ko;
        ksrc[i] = kr * D_ + ko / 2;         // elements within chunk d-window
    }

    // ---- prologue: Q tile (async) + chunk 0 (async) ----
#pragma unroll
    for (int i = 0; i < 16; i++) {
        int seg = tid + 256 * i;
        int row = seg >> 5, o = seg & 31;
        cp16(sb + SM_Q + row * QST + o * 16, Qg + row * D_ + o * 8);
    }
    cp_commit();
#pragma unroll
    for (int i = 0; i < 4; i++)
        cp16(sb + SM_K + kdst[i], KgT + ksrc[i]);
    cp_commit();

    float O[2][4];
#pragma unroll
    for (int mt = 0; mt < 2; mt++)
#pragma unroll
        for (int r = 0; r < 4; r++) O[mt][r] = 0.f;

    for (int t = 0; t < TILES_PER_SPLIT; t++) {
        float S[2][8][4];
#pragma unroll
        for (int mt = 0; mt < 2; mt++)
#pragma unroll
            for (int nb = 0; nb < 8; nb++)
#pragma unroll
                for (int r = 0; r < 4; r++) S[mt][nb][r] = 0.f;

        for (int c4 = 0; c4 < 4; c4++) {
            const int c = t * 4 + c4;
            cp_wait0();                     // chunk c landed
            __syncthreads();                // all warps done with chunk c-1
            // Stage this tile's V = [x, y, 1, 0..] (consumed in epilogue,
            // 3 barriers later; prior tile's epilogue finished before the
            // barrier above, so single-buffer is safe).
            if (c4 == 0 && tid < 128) {
                float2 cc = Cg2[t * 128 + tid];
                sts128(sb + SM_V + tid * 16,
                       bf2(cc.x, cc.y), 0x00003F80u, 0u, 0u);
            }
            if (c + 1 < CHUNKS2) {
                int nc = c + 1;
                uint32_t slot = sb + SM_K + (nc & 1) * SLOT2;
                const __nv_bfloat16* src =
                    KgT + (nc >> 2) * (128 * D_) + (nc & 3) * 64;
#pragma unroll
                for (int i = 0; i < 4; i++)
                    cp16(slot + kdst[i], src + ksrc[i]);
                cp_commit();
            }

            const uint32_t slot = sb + SM_K + (c & 1) * SLOT2;
#pragma unroll
            for (int ks = 0; ks < 4; ks++) {
                const int kbase_a = c4 * 128 + ks * 32;  // Q: full-d rows
                const int kbase_b = ks * 32;             // K slot: 64-d rows
                uint32_t a[2][4];
                LDSM_X4(a[0][0], a[0][1], a[0][2], a[0][3], qlm + kbase_a);
                LDSM_X4(a[1][0], a[1][1], a[1][2], a[1][3],
                        qlm + 16 * QST + kbase_a);
#pragma unroll
                for (int nbp = 0; nbp < 4; nbp++) {
                    uint32_t b0, b1, c0, c1;
                    LDSM_X4(b0, b1, c0, c1,
                            slot + klm + nbp * 16 * KST2 + kbase_b);
                    MMA_BF16(S[0][2 * nbp],     a[0][0], a[0][1], a[0][2],
                             a[0][3], b0, b1);
                    MMA_BF16(S[0][2 * nbp + 1], a[0][0], a[0][1], a[0][2],
                             a[0][3], c0, c1);
                    MMA_BF16(S[1][2 * nbp],     a[1][0], a[1][1], a[1][2],
                             a[1][3], b0, b1);
                    MMA_BF16(S[1][2 * nbp + 1], a[1][0], a[1][1], a[1][2],
                             a[1][3], c0, c1);
                }
            }
        }

        // ---- epilogue: p = ex2(s*scale); PV via tensor pipe ----
        // C-frag of S == A-frag layout: a0=bf2(c0,c1)|nb, a1=bf2(c2,c3)|nb,
        // a2/a3 from nb+1. B from V via ldmatrix.trans.
        uint32_t vb[4][2];
#pragma unroll
        for (int kg = 0; kg < 4; kg++)
            LDSM_X2_TRANS(vb[kg][0], vb[kg][1], vlm + kg * 256);
#pragma unroll
        for (int mt = 0; mt < 2; mt++)
#pragma unroll
            for (int nbp = 0; nbp < 4; nbp++) {
                float p0 = ex2f(S[mt][2 * nbp][0] * SCALE_EX2);
                float p1 = ex2f(S[mt][2 * nbp][1] * SCALE_EX2);
                float p2 = ex2f(S[mt][2 * nbp][2] * SCALE_EX2);
                float p3 = ex2f(S[mt][2 * nbp][3] * SCALE_EX2);
                float q0 = ex2f(S[mt][2 * nbp + 1][0] * SCALE_EX2);
                float q1 = ex2f(S[mt][2 * nbp + 1][1] * SCALE_EX2);
                float q2 = ex2f(S[mt][2 * nbp + 1][2] * SCALE_EX2);
                float q3 = ex2f(S[mt][2 * nbp + 1][3] * SCALE_EX2);
                uint32_t a0 = bf2(p0, p1), a1 = bf2(p2, p3);
                uint32_t a2 = bf2(q0, q1), a3 = bf2(q2, q3);
                MMA_BF16(O[mt], a0, a1, a2, a3, vb[nbp][0], vb[nbp][1]);
            }
    }

    // ---- extract (l, ax, ay) + cross-warpn reduction (red overlays K) ----
    // t4=0 lane: cols 0,1 = (ax, ay); t4=1 lane: col 2 = l (c0/c2).
    float4* __restrict__ red = (float4*)(smem + SM_R);
    __syncthreads();                        // K-slot loads done before overlay
#pragma unroll
    for (int mt = 0; mt < 2; mt++)
#pragma unroll
        for (int half = 0; half < 2; half++) {
            float axv = O[mt][half * 2 + 0];
            float ayv = O[mt][half * 2 + 1];
            float lv  = __shfl_sync(0xffffffffu, O[mt][half * 2],
                                    (lane & 28) | 1);
            if (t4 == 0) {
                int rowl = warpm * 32 + mt * 16 + half * 8 + g;
                red[warpn * 128 + rowl] = make_float4(lv, axv, ayv, 0.f);
            }
        }
    __syncthreads();

    if (tid < 128) {
        float4 r0 = red[tid], r1 = red[128 + tid];
        g_part[split][b * L_ + q0 + tid] =
            make_float4(r0.x + r1.x, r0.y + r1.y, r0.z + r1.z, 0.f);
    }
    __threadfence();
    __syncthreads();
    if (tid == 0)
        s_last = atomicAdd(&g_cnt[b * 32 + blockIdx.x], 1);
    __syncthreads();

    // Last-arriving split CTA merges all partials and writes outputs.
    if (s_last == NSPLIT - 1 && tid < 128) {
        int i = b * L_ + q0 + tid;
        float lv = 0.f, axv = 0.f, ayv = 0.f;
#pragma unroll
        for (int sp = 0; sp < NSPLIT; sp++) {
            float4 p = g_part[sp][i];
            lv += p.x; axv += p.y; ayv += p.z;
        }
        float a = 1.0f / (1.0f + __expf(-alpha_p[0]));
        float inv = 1.0f / lv;
        float wx = axv * inv, wy = ayv * inv;
        float2 c = ((const float2*)coords)[i];
        float nx = a * wx + (1.0f - a) * c.x;
        float ny = a * wy + (1.0f - a) * c.y;
        out_new[2 * i + 0]  = nx;
        out_new[2 * i + 1]  = ny;
        out_disp[2 * i + 0] = nx - c.x;
        out_disp[2 * i + 1] = ny - c.y;
    }
}

// ---------------------------------------------------------------------------
// Inputs: latents, current_coords, Wq, Wk, alpha_raw, layer_idx.
// Output: concat(new_coords[B,L,2], displacement[B,L,2]) fp32.
// ---------------------------------------------------------------------------
extern "C" void kernel_launch(void* const* d_in, const int* in_sizes, int n_in,
                              void* d_out, int out_size) {
    const float* latents   = (const float*)d_in[0];
    const float* coords    = (const float*)d_in[1];
    const float* Wq        = (const float*)d_in[2];
    const float* Wk        = (const float*)d_in[3];
    const float* alpha_raw = (const float*)d_in[4];
    float* out = (float*)d_out;

    convert_kernel<<<(2 * WPAIRS) / 256, 256>>>(Wq, Wk);

    cudaFuncSetAttribute(proj_mma_kernel,
                         cudaFuncAttributeMaxDynamicSharedMemorySize, P_TOT);
    proj_mma_kernel<<<BL_ / 128, 512, P_TOT>>>(latents);

    cudaFuncSetAttribute(attn_kernel,
                         cudaFuncAttributeMaxDynamicSharedMemorySize, SM_TOT);
    attn_kernel<<<dim3(L_ / 128, B_, NSPLIT), 256, SM_TOT>>>(
        coords, alpha_raw, out, out + BL_ * 2);
}

// round 16
// speedup vs baseline: 1.6596x; 1.0778x over previous
#include <cuda_runtime.h>
#include <cuda_bf16.h>
#include <math_constants.h>
#include <cstdint>

#define B_  4
#define L_  4096
#define D_  256
#define BL_ (B_ * L_)
#define NSPLIT 8
#define KEYS_PER_SPLIT (L_ / NSPLIT)            /* 512 */
#define TILES_PER_SPLIT (KEYS_PER_SPLIT / 128)  /* 4 */
#define CHUNKS2 (TILES_PER_SPLIT * 4)           /* 16 x 64-d chunks */

// g_Q / g_KB / g_Wqb / g_Wkb: PLAIN row-major bf16 (ldmatrix layout).
__device__ __align__(1024) __nv_bfloat16 g_Q[BL_ * D_];
__device__ __align__(1024) __nv_bfloat16 g_KB[BL_ * D_];
__device__ __align__(1024) __nv_bfloat16 g_Wqb[D_ * D_];
__device__ __align__(1024) __nv_bfloat16 g_Wkb[D_ * D_];
__device__ __align__(1024) float4 g_part[NSPLIT][BL_];   // (l, ax, ay)
__device__ int g_cnt[B_ * 32];                           // merge counters

// ---------------------------------------------------------------------------
// helpers
// ---------------------------------------------------------------------------
__device__ __forceinline__ uint32_t smem_u32(const void* p) {
    uint32_t a;
    asm("{ .reg .u64 t; cvta.to.shared.u64 t, %1; cvt.u32.u64 %0, t; }"
        : "=r"(a) : "l"(p));
    return a;
}

__device__ __forceinline__ float ex2f(float x) {
    float y;
    asm("ex2.approx.f32 %0, %1;" : "=f"(y) : "f"(x));
    return y;
}

__device__ __forceinline__ void cp16(uint32_t dst, const void* src) {
    asm volatile("cp.async.cg.shared.global [%0], [%1], 16;"
                 :: "r"(dst), "l"(src) : "memory");
}
__device__ __forceinline__ void cp_commit() {
    asm volatile("cp.async.commit_group;" ::: "memory");
}
__device__ __forceinline__ void cp_wait0() {
    asm volatile("cp.async.wait_group 0;" ::: "memory");
}

__device__ __forceinline__ void sts128(uint32_t a, uint32_t r0, uint32_t r1,
                                       uint32_t r2, uint32_t r3) {
    asm volatile("st.shared.v4.b32 [%0], {%1, %2, %3, %4};"
                 :: "r"(a), "r"(r0), "r"(r1), "r"(r2), "r"(r3) : "memory");
}

#define LDSM_X4(r0, r1, r2, r3, addr) \
    asm volatile("ldmatrix.sync.aligned.m8n8.x4.shared.b16 " \
                 "{%0, %1, %2, %3}, [%4];" \
                 : "=r"(r0), "=r"(r1), "=r"(r2), "=r"(r3) : "r"(addr))

#define LDSM_X2_TRANS(r0, r1, addr) \
    asm volatile("ldmatrix.sync.aligned.m8n8.x2.trans.shared.b16 " \
                 "{%0, %1}, [%2];" \
                 : "=r"(r0), "=r"(r1) : "r"(addr))

#define MMA_BF16(d, a0, a1, a2, a3, b0, b1) \
    asm volatile("mma.sync.aligned.m16n8k16.row.col.f32.bf16.bf16.f32 " \
                 "{%0,%1,%2,%3},{%4,%5,%6,%7},{%8,%9},{%0,%1,%2,%3};" \
                 : "+f"((d)[0]), "+f"((d)[1]), "+f"((d)[2]), "+f"((d)[3]) \
                 : "r"(a0), "r"(a1), "r"(a2), "r"(a3), "r"(b0), "r"(b1))

__device__ __forceinline__ uint32_t bf2(float lo, float hi) {
    __nv_bfloat162 v = __floats2bfloat162_rn(lo, hi);
    return *(uint32_t*)&v;
}

// ---------------------------------------------------------------------------
// Kernel 0: round Wq / Wk to bf16 plain row-major; zero merge counters.
// ---------------------------------------------------------------------------
#define WPAIRS (D_ * 128)

__global__ void __launch_bounds__(256)
convert_kernel(const float* __restrict__ Wq, const float* __restrict__ Wk) {
    int idx = blockIdx.x * 256 + threadIdx.x;     // 0 .. 2*WPAIRS-1
    if (idx < B_ * 32) g_cnt[idx] = 0;
    const float* src = (idx < WPAIRS) ? Wq : Wk;
    __nv_bfloat162* dst = (__nv_bfloat162*)((idx < WPAIRS) ? g_Wqb : g_Wkb);
    int i = (idx < WPAIRS) ? idx : idx - WPAIRS;
    float2 v = __ldg((const float2*)src + i);
    dst[i] = __floats2bfloat162_rn(v.x, v.y);
}

// ---------------------------------------------------------------------------
// Kernel 1: proj via mma.sync bf16 + ldmatrix. One CTA = 128 rows x BOTH
// Wq and Wk. W streamed in 8 x 64-d chunks (4 Wq + 4 Wk), true double
// buffer (ring-2, wait_group 0, prefetch-1) — same scheme as attn.
// X read fp32 directly from latents (LDG -> bf16 pack -> plain STS).
// Row L2-norm fused; output PLAIN row-major to g_Q / g_KB.
// 512 threads = 16 warps (warpm 0..3 x warpn 0..3), warp tile 32m x 64n.
// NOTE: X rows hold all 256 d (kbase_a = c2*128 + ks*32 bytes); W slot
// rows hold ONLY the 64-d chunk window (kbase_b = ks*32 bytes).
// ---------------------------------------------------------------------------
#define PXST 528                             /* X row bytes (512 + 16) */
#define PWST2 144                            /* W row bytes (128 + 16) */
#define P_SLOT (D_ * PWST2)                  /* 36864 */
#define P_SMX 0
#define P_SMW (128 * PXST)                   /* 67584 */
#define P_RED (P_SMW + 2 * P_SLOT)           /* 141312 */
#define P_TOT (P_RED + 2048)                 /* 143360 */

__global__ void __launch_bounds__(512, 1)
proj_mma_kernel(const float* __restrict__ latents) {
    extern __shared__ __align__(1024) char smem[];
    const uint32_t sb = smem_u32(smem);
    const int tid  = threadIdx.x;
    const int lane = tid & 31;
    const int warp = tid >> 5;
    const int warpm = warp & 3, warpn = warp >> 2;   // 4 x 4
    const int g  = lane >> 2, t4 = lane & 3;
    const int row0 = blockIdx.x * 128;

    // ldmatrix lane-address bases (same scheme as attn).
    const uint32_t qlm = sb + P_SMX +
        (warpm * 32 + (lane & 15)) * PXST + (lane >> 4) * 16;
    const uint32_t klm =
        (warpn * 64 + ((lane >> 4) << 3) + (lane & 7)) * PWST2 +
        ((lane >> 3) & 1) * 16;

    // W-chunk cp.async offsets: 2048 cp16 per 64-d chunk, 4 per thread.
    uint32_t wdst[4];
    int wsrc[4];
#pragma unroll
    for (int i = 0; i < 4; i++) {
        int seg = tid + 512 * i;            // 0..2047; 8 x 16B per W row
        int wr = seg >> 3, wo = (seg & 7) * 16;
        wdst[i] = wr * PWST2 + wo;
        wsrc[i] = wr * D_ + wo / 2;         // elements within chunk d-window
    }

    // ---- prologue: W chunk 0 (async) + X fp32->bf16 plain STS ----
#pragma unroll
    for (int i = 0; i < 4; i++)
        cp16(sb + P_SMW + wdst[i], g_Wqb + wsrc[i]);
    cp_commit();
    {
        const float4* __restrict__ Xf4 =
            (const float4*)(latents + (size_t)row0 * D_);
#pragma unroll
        for (int i = 0; i < 4; i++) {
            int idx = tid + 512 * i;            // 0..2047
            int r = idx >> 4, gg = idx & 15;    // row, 16-d group
            const float4* p = Xf4 + r * 64 + gg * 4;
            float4 v0 = __ldg(p + 0), v1 = __ldg(p + 1);
            float4 v2 = __ldg(p + 2), v3 = __ldg(p + 3);
            uint32_t sa = sb + P_SMX + r * PXST + gg * 32;
            sts128(sa,      bf2(v0.x, v0.y), bf2(v0.z, v0.w),
                            bf2(v1.x, v1.y), bf2(v1.z, v1.w));
            sts128(sa + 16, bf2(v2.x, v2.y), bf2(v2.z, v2.w),
                            bf2(v3.x, v3.y), bf2(v3.z, v3.w));
        }
    }

    float* __restrict__ red = (float*)(smem + P_RED);

    for (int which = 0; which < 2; which++) {
        float S[2][8][4];
#pragma unroll
        for (int mt = 0; mt < 2; mt++)
#pragma unroll
            for (int nb = 0; nb < 8; nb++)
#pragma unroll
                for (int r = 0; r < 4; r++) S[mt][nb][r] = 0.f;

        for (int c2 = 0; c2 < 4; c2++) {
            const int gc = which * 4 + c2;
            cp_wait0();                     // chunk gc landed
            __syncthreads();                // all warps done with chunk gc-1
            if (gc + 1 < 8) {
                int nc = gc + 1;
                uint32_t slot = sb + P_SMW + (nc & 1) * P_SLOT;
                const __nv_bfloat16* src =
                    (nc < 4 ? g_Wqb : g_Wkb) + (nc & 3) * 64;
#pragma unroll
                for (int i = 0; i < 4; i++)
                    cp16(slot + wdst[i], src + wsrc[i]);
                cp_commit();
            }

            const uint32_t slot = sb + P_SMW + (gc & 1) * P_SLOT;
#pragma unroll
            for (int ks = 0; ks < 4; ks++) {
                const int kbase_a = c2 * 128 + ks * 32;  // X: full-d rows
                const int kbase_b = ks * 32;             // W slot: 64-d rows
                uint32_t a[2][4];
                LDSM_X4(a[0][0], a[0][1], a[0][2], a[0][3], qlm + kbase_a);
                LDSM_X4(a[1][0], a[1][1], a[1][2], a[1][3],
                        qlm + 16 * PXST + kbase_a);
#pragma unroll
                for (int nbp = 0; nbp < 4; nbp++) {
                    uint32_t b0, b1, c0, c1;
                    LDSM_X4(b0, b1, c0, c1,
                            slot + klm + nbp * 16 * PWST2 + kbase_b);
                    MMA_BF16(S[0][2 * nbp],     a[0][0], a[0][1], a[0][2],
                             a[0][3], b0, b1);
                    MMA_BF16(S[0][2 * nbp + 1], a[0][0], a[0][1], a[0][2],
                             a[0][3], c0, c1);
                    MMA_BF16(S[1][2 * nbp],     a[1][0], a[1][1], a[1][2],
                             a[1][3], b0, b1);
                    MMA_BF16(S[1][2 * nbp + 1], a[1][0], a[1][1], a[1][2],
                             a[1][3], c0, c1);
                }
            }
        }

        // ---- row sum-of-squares: quad shfl + cross-warpn exchange ----
        __syncthreads();   // last chunk's loads done before red reuse below
#pragma unroll
        for (int mt = 0; mt < 2; mt++)
#pragma unroll
            for (int h = 0; h < 2; h++) {
                float v = 0.f;
#pragma unroll
                for (int nb = 0; nb < 8; nb++) {
                    v = fmaf(S[mt][nb][2 * h], S[mt][nb][2 * h], v);
                    v = fmaf(S[mt][nb][2 * h + 1], S[mt][nb][2 * h + 1], v);
                }
                v += __shfl_xor_sync(0xffffffffu, v, 1);
                v += __shfl_xor_sync(0xffffffffu, v, 2);
                if (t4 == 0)
                    red[warpn * 128 + warpm * 32 + mt * 16 + h * 8 + g] = v;
            }
        __syncthreads();

        // PLAIN row-major output: S[mt][nb] covers cols warpn*64+nb*8+2t4(+1)
        // -> pair index j = warpn*32 + nb*4 + t4.
        __nv_bfloat162* __restrict__ Out =
            (__nv_bfloat162*)(which ? g_KB : g_Q);
#pragma unroll
        for (int mt = 0; mt < 2; mt++)
#pragma unroll
            for (int h = 0; h < 2; h++) {
                int rowl = warpm * 32 + mt * 16 + h * 8 + g;
                float tot = (red[rowl] + red[128 + rowl]) +
                            (red[256 + rowl] + red[384 + rowl]);
                float scale = 1.0f / fmaxf(sqrtf(tot), 1e-12f);
                __nv_bfloat162* orow = Out + (size_t)(row0 + rowl) * 128;
#pragma unroll
                for (int nb = 0; nb < 8; nb++) {
                    int j = warpn * 32 + nb * 4 + t4;
                    orow[j] = __floats2bfloat162_rn(
                        S[mt][nb][2 * h] * scale, S[mt][nb][2 * h + 1] * scale);
                }
            }
        __syncthreads();   // red reads done before next pass writes
    }
}

// ---------------------------------------------------------------------------
// Kernel 2: flash attention partials + fused finalize (last CTA merges).
// Grid (32 qtiles, B, NSPLIT=8); 2 CTAs co-resident per SM (fine-grained
// CTAs -> ceil(1024/148)=7 per SM -> near-perfect wave packing).
// QK fragments via ldmatrix.x4; PV contraction on the tensor pipe
// (S C-frag == A-frag identity; V = [x, y, 1, 0..] via ldmatrix.x2.trans).
// ---------------------------------------------------------------------------
#define QST   528
#define KST2  144                            /* 128B data + 16 pad */
#define SLOT2 (128 * KST2)                   /* 18432 */
#define SM_Q   0
#define SM_K   (128 * QST)                   /* 67584 */
#define SM_V   (SM_K + 2 * SLOT2)            /* 104448 */
#define SM_R   SM_K                          /* overlay on dead K slots */
#define SM_TOT (SM_V + 2048)                 /* 106496 */

#define SCALE_EX2 14.4269504088896340f       /* 10 * log2(e) */

__global__ void __launch_bounds__(256, 2)
attn_kernel(const float* __restrict__ coords,
            const float* __restrict__ alpha_p,
            float* __restrict__ out_new,
            float* __restrict__ out_disp) {
    extern __shared__ __align__(1024) char smem[];
    __shared__ int s_last;
    const uint32_t sb = smem_u32(smem);
    const int tid  = threadIdx.x;
    const int lane = tid & 31;
    const int warp = tid >> 5;
    const int warpm = warp & 3, warpn = warp >> 2;
    const int g  = lane >> 2, t4 = lane & 3;
    const int b  = blockIdx.y;
    const int q0 = blockIdx.x * 128;
    const int split = blockIdx.z;

    const __nv_bfloat16* __restrict__ Qg = g_Q + (size_t)(b * L_ + q0) * D_;
    const __nv_bfloat16* __restrict__ KgT =
        g_KB + (size_t)(b * L_ + split * KEYS_PER_SPLIT) * D_;
    const float2* __restrict__ Cg2 = (const float2*)coords + (size_t)b * L_ +
                                     split * KEYS_PER_SPLIT;

    // ldmatrix lane-address bases.
    const uint32_t qlm = sb + SM_Q +
        (warpm * 32 + (lane & 15)) * QST + (lane >> 4) * 16;
    const uint32_t klm =
        (warpn * 64 + ((lane >> 4) << 3) + (lane & 7)) * KST2 +
        ((lane >> 3) & 1) * 16;
    // V tile (128 x 8 bf16, 16B rows): lanes 0-15 supply key-row addresses.
    const uint32_t vlm = sb + SM_V + (warpn * 64 + (lane & 15)) * 16;

    // K-chunk cp.async offsets: 1024 cp16 per 64-d chunk, 4 per thread.
    uint32_t kdst[4];
    int ksrc[4];
#pragma unroll
    for (int i = 0; i < 4; i++) {
        int seg = tid + 256 * i;            // 0..1023; 8 x 16B per key row
        int kr = seg >> 3, ko = (seg & 7) * 16;
        kdst[i] = kr * KST2 + ko;
        ksrc[i] = kr * D_ + ko / 2;         // elements within chunk d-window
    }

    // ---- prologue: Q tile (async) + chunk 0 (async) ----
#pragma unroll
    for (int i = 0; i < 16; i++) {
        int seg = tid + 256 * i;
        int row = seg >> 5, o = seg & 31;
        cp16(sb + SM_Q + row * QST + o * 16, Qg + row * D_ + o * 8);
    }
    cp_commit();
#pragma unroll
    for (int i = 0; i < 4; i++)
        cp16(sb + SM_K + kdst[i], KgT + ksrc[i]);
    cp_commit();

    float O[2][4];
#pragma unroll
    for (int mt = 0; mt < 2; mt++)
#pragma unroll
        for (int r = 0; r < 4; r++) O[mt][r] = 0.f;

    for (int t = 0; t < TILES_PER_SPLIT; t++) {
        float S[2][8][4];
#pragma unroll
        for (int mt = 0; mt < 2; mt++)
#pragma unroll
            for (int nb = 0; nb < 8; nb++)
#pragma unroll
                for (int r = 0; r < 4; r++) S[mt][nb][r] = 0.f;

        for (int c4 = 0; c4 < 4; c4++) {
            const int c = t * 4 + c4;
            cp_wait0();                     // chunk c landed
            __syncthreads();                // all warps done with chunk c-1
            // Stage this tile's V = [x, y, 1, 0..] (consumed in epilogue).
            if (c4 == 0 && tid < 128) {
                float2 cc = Cg2[t * 128 + tid];
                sts128(sb + SM_V + tid * 16,
                       bf2(cc.x, cc.y), 0x00003F80u, 0u, 0u);
            }
            if (c + 1 < CHUNKS2) {
                int nc = c + 1;
                uint32_t slot = sb + SM_K + (nc & 1) * SLOT2;
                const __nv_bfloat16* src =
                    KgT + (nc >> 2) * (128 * D_) + (nc & 3) * 64;
#pragma unroll
                for (int i = 0; i < 4; i++)
                    cp16(slot + kdst[i], src + ksrc[i]);
                cp_commit();
            }

            const uint32_t slot = sb + SM_K + (c & 1) * SLOT2;
#pragma unroll
            for (int ks = 0; ks < 4; ks++) {
                const int kbase_a = c4 * 128 + ks * 32;  // Q: full-d rows
                const int kbase_b = ks * 32;             // K slot: 64-d rows
                uint32_t a[2][4];
                LDSM_X4(a[0][0], a[0][1], a[0][2], a[0][3], qlm + kbase_a);
                LDSM_X4(a[1][0], a[1][1], a[1][2], a[1][3],
                        qlm + 16 * QST + kbase_a);
#pragma unroll
                for (int nbp = 0; nbp < 4; nbp++) {
                    uint32_t b0, b1, c0, c1;
                    LDSM_X4(b0, b1, c0, c1,
                            slot + klm + nbp * 16 * KST2 + kbase_b);
                    MMA_BF16(S[0][2 * nbp],     a[0][0], a[0][1], a[0][2],
                             a[0][3], b0, b1);
                    MMA_BF16(S[0][2 * nbp + 1], a[0][0], a[0][1], a[0][2],
                             a[0][3], c0, c1);
                    MMA_BF16(S[1][2 * nbp],     a[1][0], a[1][1], a[1][2],
                             a[1][3], b0, b1);
                    MMA_BF16(S[1][2 * nbp + 1], a[1][0], a[1][1], a[1][2],
                             a[1][3], c0, c1);
                }
            }
        }

        // ---- epilogue: p = ex2(s*scale); PV via tensor pipe ----
        uint32_t vb[4][2];
#pragma unroll
        for (int kg = 0; kg < 4; kg++)
            LDSM_X2_TRANS(vb[kg][0], vb[kg][1], vlm + kg * 256);
#pragma unroll
        for (int mt = 0; mt < 2; mt++)
#pragma unroll
            for (int nbp = 0; nbp < 4; nbp++) {
                float p0 = ex2f(S[mt][2 * nbp][0] * SCALE_EX2);
                float p1 = ex2f(S[mt][2 * nbp][1] * SCALE_EX2);
                float p2 = ex2f(S[mt][2 * nbp][2] * SCALE_EX2);
                float p3 = ex2f(S[mt][2 * nbp][3] * SCALE_EX2);
                float q0 = ex2f(S[mt][2 * nbp + 1][0] * SCALE_EX2);
                float q1 = ex2f(S[mt][2 * nbp + 1][1] * SCALE_EX2);
                float q2 = ex2f(S[mt][2 * nbp + 1][2] * SCALE_EX2);
                float q3 = ex2f(S[mt][2 * nbp + 1][3] * SCALE_EX2);
                uint32_t a0 = bf2(p0, p1), a1 = bf2(p2, p3);
                uint32_t a2 = bf2(q0, q1), a3 = bf2(q2, q3);
                MMA_BF16(O[mt], a0, a1, a2, a3, vb[nbp][0], vb[nbp][1]);
            }
    }

    // ---- extract (l, ax, ay) + cross-warpn reduction (red overlays K) ----
    float4* __restrict__ red = (float4*)(smem + SM_R);
    __syncthreads();                        // K-slot loads done before overlay
#pragma unroll
    for (int mt = 0; mt < 2; mt++)
#pragma unroll
        for (int half = 0; half < 2; half++) {
            float axv = O[mt][half * 2 + 0];
            float ayv = O[mt][half * 2 + 1];
            float lv  = __shfl_sync(0xffffffffu, O[mt][half * 2],
                                    (lane & 28) | 1);
            if (t4 == 0) {
                int rowl = warpm * 32 + mt * 16 + half * 8 + g;
                red[warpn * 128 + rowl] = make_float4(lv, axv, ayv, 0.f);
            }
        }
    __syncthreads();

    if (tid < 128) {
        float4 r0 = red[tid], r1 = red[128 + tid];
        g_part[split][b * L_ + q0 + tid] =
            make_float4(r0.x + r1.x, r0.y + r1.y, r0.z + r1.z, 0.f);
    }
    __threadfence();
    __syncthreads();
    if (tid == 0)
        s_last = atomicAdd(&g_cnt[b * 32 + blockIdx.x], 1);
    __syncthreads();

    // Last-arriving split CTA merges all partials and writes outputs.
    if (s_last == NSPLIT - 1 && tid < 128) {
        int i = b * L_ + q0 + tid;
        float lv = 0.f, axv = 0.f, ayv = 0.f;
#pragma unroll
        for (int sp = 0; sp < NSPLIT; sp++) {
            float4 p = g_part[sp][i];
            lv += p.x; axv += p.y; ayv += p.z;
        }
        float a = 1.0f / (1.0f + __expf(-alpha_p[0]));
        float inv = 1.0f / lv;
        float wx = axv * inv, wy = ayv * inv;
        float2 c = ((const float2*)coords)[i];
        float nx = a * wx + (1.0f - a) * c.x;
        float ny = a * wy + (1.0f - a) * c.y;
        out_new[2 * i + 0]  = nx;
        out_new[2 * i + 1]  = ny;
        out_disp[2 * i + 0] = nx - c.x;
        out_disp[2 * i + 1] = ny - c.y;
    }
}

// ---------------------------------------------------------------------------
// Inputs: latents, current_coords, Wq, Wk, alpha_raw, layer_idx.
// Output: concat(new_coords[B,L,2], displacement[B,L,2]) fp32.
// ---------------------------------------------------------------------------
extern "C" void kernel_launch(void* const* d_in, const int* in_sizes, int n_in,
                              void* d_out, int out_size) {
    const float* latents   = (const float*)d_in[0];
    const float* coords    = (const float*)d_in[1];
    const float* Wq        = (const float*)d_in[2];
    const float* Wk        = (const float*)d_in[3];
    const float* alpha_raw = (const float*)d_in[4];
    float* out = (float*)d_out;

    convert_kernel<<<(2 * WPAIRS) / 256, 256>>>(Wq, Wk);

    cudaFuncSetAttribute(proj_mma_kernel,
                         cudaFuncAttributeMaxDynamicSharedMemorySize, P_TOT);
    proj_mma_kernel<<<BL_ / 128, 512, P_TOT>>>(latents);

    cudaFuncSetAttribute(attn_kernel,
                         cudaFuncAttributeMaxDynamicSharedMemorySize, SM_TOT);
    attn_kernel<<<dim3(L_ / 128, B_, NSPLIT), 256, SM_TOT>>>(
        coords, alpha_raw, out, out + BL_ * 2);
}